// round 6
// baseline (speedup 1.0000x reference)
#include <cuda_runtime.h>
#include <mma.h>
#include <cstdint>
#include <math.h>

using namespace nvcuda;

#define Hdim 1024
#define INdim 512
#define Bdim 256
#define Tdim 256
#define HB (Hdim * Bdim)          // 262144 elements
#define KSPLIT 4
#define XT_STRIDE (INdim * Bdim)  // 131072 floats per timestep of x

// ---------------- device scratch (no cudaMalloc allowed) ----------------
// NOTE: these are ONLY referenced inside device code. Passing a __device__
// global as a host-side kernel argument yields the HOST shadow address,
// which GB300's ATS silently honors -> GEMM results vanish into host RAM.
// That was the R4/R5 bug.
__device__ __align__(1024) float g_Az[(size_t)Tdim * HB];   // 256 MiB
__device__ __align__(1024) float g_Ar[(size_t)Tdim * HB];   // 256 MiB
__device__ __align__(1024) float g_r[HB];
__device__ __align__(1024) float g_m[HB];
__device__ __align__(1024) float g_G1p[KSPLIT * HB];
__device__ __align__(1024) float g_G2p[KSPLIT * HB];
__device__ __align__(128) float g_X[HB];
__device__ __align__(128) float g_U[HB];
__device__ __align__(128) float g_v[HB];

// ---------------- helpers ----------------
__device__ __forceinline__ float sigm(float x) {
    return 1.0f / (1.0f + __expf(-x));
}
__device__ __forceinline__ float totf32(float x) {
    uint32_t o;
    asm("cvt.rna.tf32.f32 %0, %1;" : "=r"(o) : "f"(x));
    return __uint_as_float(o);
}

// ---------------- init state ----------------
__global__ void init_state_kernel() {
    int i = blockIdx.x * blockDim.x + threadIdx.x;
    g_X[i] = 1.0f;
    g_U[i] = 0.9f;
    g_v[i] = 0.0f;
}

// ---------------- wmma tf32 GEMM -----------------------------------------
// C tile [128 x 64] = A[128 x kCount] @ B[kCount x 64], fp32 accumulate.
// A row-major (harness pointer, ld=Kd). B/C row-major ld=256, bound to
// device globals IN DEVICE CODE via MODE:
//   MODE 0 (input proj): B = x + q*XT_STRIDE,  C = (which? g_Ar:g_Az) + q*HB
//                        kStart = 0, kCount = 512, q = timestep
//   MODE 1 (recurrence): B = which? g_m : g_r, C = (which? g_G2p:g_G1p)+q*HB
//                        kStart = q*(Hdim/KSPLIT), kCount = Hdim/KSPLIT
// grid (8, 4, 2*Q): mb, nb, z; which = z&1, q = z>>1.
template <int MODE>
__global__ __launch_bounds__(256) void gemm_wmma(
    const float* __restrict__ A0, const float* __restrict__ A1,
    const float* __restrict__ xp, int Kd)
{
    const int warp = threadIdx.x >> 5;
    const int wm = warp >> 1;   // 0..3
    const int wn = warp & 1;    // 0..1
    const int mb = blockIdx.x;  // 0..7
    const int nb = blockIdx.y;  // 0..3
    const int z = blockIdx.z;
    const int which = z & 1;
    const int q = z >> 1;

    const float* A = which ? A1 : A0;
    const float* B;
    float* C;
    int kStart, kCount;
    if (MODE == 0) {
        B = xp + (size_t)q * XT_STRIDE;
        C = (which ? g_Ar : g_Az) + (size_t)q * HB;
        kStart = 0;
        kCount = INdim;
    } else {
        B = which ? g_m : g_r;
        C = (which ? g_G2p : g_G1p) + (size_t)q * HB;
        kCount = Hdim / KSPLIT;
        kStart = q * kCount;
    }
    const int kEnd = kStart + kCount;

    const int row = mb * 128 + wm * 32;
    const int col = nb * 64 + wn * 32;

    wmma::fragment<wmma::accumulator, 16, 16, 8, float> acc[2][2];
#pragma unroll
    for (int i = 0; i < 2; ++i)
#pragma unroll
        for (int j = 0; j < 2; ++j) wmma::fill_fragment(acc[i][j], 0.0f);

    for (int k = kStart; k < kEnd; k += 8) {
        wmma::fragment<wmma::matrix_a, 16, 16, 8, wmma::precision::tf32,
                       wmma::row_major> af[2];
        wmma::fragment<wmma::matrix_b, 16, 16, 8, wmma::precision::tf32,
                       wmma::row_major> bf[2];
#pragma unroll
        for (int i = 0; i < 2; ++i) {
            wmma::load_matrix_sync(af[i], A + (size_t)(row + i * 16) * Kd + k, Kd);
#pragma unroll
            for (int e = 0; e < af[i].num_elements; ++e)
                af[i].x[e] = totf32(af[i].x[e]);
        }
#pragma unroll
        for (int j = 0; j < 2; ++j) {
            wmma::load_matrix_sync(bf[j], B + (size_t)k * Bdim + col + j * 16, Bdim);
#pragma unroll
            for (int e = 0; e < bf[j].num_elements; ++e)
                bf[j].x[e] = totf32(bf[j].x[e]);
        }
#pragma unroll
        for (int i = 0; i < 2; ++i)
#pragma unroll
            for (int j = 0; j < 2; ++j)
                wmma::mma_sync(acc[i][j], af[i], bf[j], acc[i][j]);
    }

#pragma unroll
    for (int i = 0; i < 2; ++i)
#pragma unroll
        for (int j = 0; j < 2; ++j)
            wmma::store_matrix_sync(C + (size_t)(row + i * 16) * Bdim + col + j * 16,
                                    acc[i][j], Bdim, wmma::mem_row_major);
}

// ---------------- elementwise step (epilogue t-1 fused with prep t) ------
__global__ __launch_bounds__(256) void step_elem(
    const float* __restrict__ c_x, const float* __restrict__ c_u,
    const float* __restrict__ c_U, const float* __restrict__ gz,
    const float* __restrict__ br, int t)
{
    const int idx = blockIdx.x * 256 + threadIdx.x;
    const int h = idx >> 8;

    float v = g_v[idx];
    if (t > 0) {
        const size_t off = (size_t)(t - 1) * HB + idx;
        float s1 = (g_G1p[idx] + g_G1p[HB + idx]) +
                   (g_G1p[2 * HB + idx] + g_G1p[3 * HB + idx]);
        float s2 = (g_G2p[idx] + g_G2p[HB + idx]) +
                   (g_G2p[2 * HB + idx] + g_G2p[3 * HB + idx]);
        float z = 0.1f * sigm(s1 + g_Az[off] + gz[h]);
        v = (1.0f - z) * v + 0.1f * (s2 + g_Ar[off] + br[h]);
        g_v[idx] = v;
        g_Az[off] = v;  // stage v for final transpose
    }
    if (t < Tdim) {
        const float r = sigm(v);
        const float zx = 0.001f + 0.099f * sigm(c_x[h]);
        const float zu = 0.001f + 0.099f * sigm(c_u[h]);
        const float Uc = 0.9f * sigm(c_U[h]);
        const float X = g_X[idx];
        const float U = g_U[idx];
        float Xn = zx + (1.0f - zx) * X - U * X * r;
        float Un = Uc * zu + (1.0f - zu) * U + Uc * (1.0f - U) * r;
        Un = fminf(fmaxf(Un, Uc), 1.0f);
        g_X[idx] = Xn;
        g_U[idx] = Un;
        g_r[idx] = r;
        g_m[idx] = Un * Xn * r;
    }
}

// ---------------- final transpose: g_Az[t][h][b] -> out[t][b][h] ---------
__global__ __launch_bounds__(256) void transpose_out(float* __restrict__ out) {
    __shared__ float tile[32][33];
    const int t = blockIdx.z;
    const int h0 = blockIdx.y * 32;
    const int b0 = blockIdx.x * 32;
    const float* src = g_Az + (size_t)t * HB;
    float* dst = out + (size_t)t * HB;
    const int lx = threadIdx.x, ly = threadIdx.y;
#pragma unroll
    for (int i = 0; i < 32; i += 8)
        tile[ly + i][lx] = src[(size_t)(h0 + ly + i) * Bdim + b0 + lx];
    __syncthreads();
#pragma unroll
    for (int i = 0; i < 32; i += 8)
        dst[(size_t)(b0 + ly + i) * Hdim + h0 + lx] = tile[lx][ly + i];
}

// ---------------- launch ----------------
extern "C" void kernel_launch(void* const* d_in, const int* in_sizes, int n_in,
                              void* d_out, int out_size)
{
    const float* x   = (const float*)d_in[0];  // (T, IN, B)
    const float* c_x = (const float*)d_in[1];
    const float* c_u = (const float*)d_in[2];
    const float* c_U = (const float*)d_in[3];
    const float* w_r = (const float*)d_in[4];  // (H,H)
    const float* p_r = (const float*)d_in[5];  // (H,IN)
    const float* b_r = (const float*)d_in[6];
    const float* g_z = (const float*)d_in[7];
    const float* Km  = (const float*)d_in[8];  // (H,H)
    const float* p_z = (const float*)d_in[9];  // (H,IN)
    float* out = (float*)d_out;                // (T, B, H)

    init_state_kernel<<<HB / 256, 256>>>();

    // input projections: Az[t] = p_z@x_t, Ar[t] = p_r@x_t (biases in step_elem)
    gemm_wmma<0><<<dim3(8, 4, 2 * Tdim), 256>>>(p_z, p_r, x, INdim);

    // recurrence: G1 = K@r, G2 = w_r@m, K-split=4 (partials in g_G1p/g_G2p)
    for (int t = 0; t < Tdim; ++t) {
        step_elem<<<Hdim, 256>>>(c_x, c_u, c_U, g_z, b_r, t);
        gemm_wmma<1><<<dim3(8, 4, 2 * KSPLIT), 256>>>(Km, w_r, nullptr, Hdim);
    }
    step_elem<<<Hdim, 256>>>(c_x, c_u, c_U, g_z, b_r, Tdim);

    transpose_out<<<dim3(Bdim / 32, Hdim / 32, Tdim), dim3(32, 8)>>>(out);
}

// round 7
// speedup vs baseline: 1.3370x; 1.3370x over previous
#include <cuda_runtime.h>
#include <mma.h>
#include <cstdint>
#include <math.h>

using namespace nvcuda;

#define Hdim 1024
#define INdim 512
#define Bdim 256
#define Tdim 256
#define HB (Hdim * Bdim)          // 262144 elements
#define KSPLIT 4
#define XT_STRIDE (INdim * Bdim)  // 131072 floats per timestep of x

#define KCHUNK 32
#define A_LD 36                   // 32 + 4 pad, multiple of 4 floats (16B)
#define B_LD 68                   // 64 + 4 pad
#define SA_FLOATS (128 * A_LD)    // 4608
#define SB_FLOATS (KCHUNK * B_LD) // 2176
#define SMEM_BYTES (2 * (SA_FLOATS + SB_FLOATS) * 4)  // 54272

// ---------------- device scratch (no cudaMalloc allowed) ----------------
// ONLY referenced in device code (host-arg binding of __device__ globals
// silently resolves to the host shadow on GB300 ATS — the R4/R5 bug).
__device__ __align__(1024) float g_Az[(size_t)Tdim * HB];          // 256 MiB
__device__ __align__(1024) float g_Ar[(size_t)Tdim * HB];          // 256 MiB
__device__ __align__(1024) float g_xr[(size_t)Tdim * XT_STRIDE];   // 128 MiB
__device__ __align__(1024) float g_Krnd[Hdim * Hdim];
__device__ __align__(1024) float g_Wrnd[Hdim * Hdim];
__device__ __align__(1024) float g_Pzr[Hdim * INdim];
__device__ __align__(1024) float g_Prr[Hdim * INdim];
__device__ __align__(1024) float g_r[HB];
__device__ __align__(1024) float g_m[HB];
__device__ __align__(1024) float g_G1p[KSPLIT * HB];
__device__ __align__(1024) float g_G2p[KSPLIT * HB];
__device__ __align__(128) float g_X[HB];
__device__ __align__(128) float g_U[HB];
__device__ __align__(128) float g_v[HB];

// ---------------- helpers ----------------
__device__ __forceinline__ float sigm(float x) {
    return 1.0f / (1.0f + __expf(-x));
}
__device__ __forceinline__ float totf32(float x) {
    uint32_t o;
    asm("cvt.rna.tf32.f32 %0, %1;" : "=r"(o) : "f"(x));
    return __uint_as_float(o);
}
__device__ __forceinline__ uint32_t s2u(const void* p) {
    return (uint32_t)__cvta_generic_to_shared(p);
}
__device__ __forceinline__ void cp_async16(uint32_t saddr, const void* g) {
    asm volatile("cp.async.ca.shared.global [%0], [%1], 16;"
                 :: "r"(saddr), "l"(g));
}
__device__ __forceinline__ void cp_commit() {
    asm volatile("cp.async.commit_group;" ::: "memory");
}
template <int N>
__device__ __forceinline__ void cp_wait() {
    asm volatile("cp.async.wait_group %0;" :: "n"(N) : "memory");
}

// ---------------- init state ----------------
__global__ void init_state_kernel() {
    int i = blockIdx.x * blockDim.x + threadIdx.x;
    g_X[i] = 1.0f;
    g_U[i] = 0.9f;
    g_v[i] = 0.0f;
}

// ---------------- one-shot tf32 rounding into device scratch -------------
__global__ __launch_bounds__(256) void round_copy(const float* __restrict__ src,
                                                  int which) {
    float* dst = which == 0 ? g_Krnd : which == 1 ? g_Wrnd
               : which == 2 ? g_Pzr  : which == 3 ? g_Prr : g_xr;
    const size_t i = (size_t)blockIdx.x * 256 + threadIdx.x;
    float4 v = ((const float4*)src)[i];
    v.x = totf32(v.x); v.y = totf32(v.y);
    v.z = totf32(v.z); v.w = totf32(v.w);
    ((float4*)dst)[i] = v;
}

// ---------------- smem-staged wmma tf32 GEMM -----------------------------
// C[128x64 tile] = A[128 x kCount] @ B[kCount x 64], fp32 accumulate.
// All operands pre-rounded tf32; bound in device code per MODE:
//  MODE 0 (proj): A = which? g_Prr:g_Pzr (ld 512), B = g_xr + q*XT_STRIDE,
//                 C = (which? g_Ar:g_Az) + q*HB, kCount=512, q = timestep
//  MODE 1 (rec):  A = which? g_Wrnd:g_Krnd (ld 1024), B = which? g_m:g_r,
//                 C = (which? g_G2p:g_G1p) + q*HB, k in [q*256, q*256+256)
// grid (8, 4, 2*Q); which = z&1, q = z>>1. cp.async double-buffered.
template <int MODE>
__global__ __launch_bounds__(256) void gemm_smem() {
    extern __shared__ float sm[];
    const int tid = threadIdx.x;
    const int warp = tid >> 5;
    const int wm = warp >> 1;   // 0..3
    const int wn = warp & 1;    // 0..1
    const int mb = blockIdx.x;  // 0..7
    const int nb = blockIdx.y;  // 0..3
    const int z = blockIdx.z;
    const int which = z & 1;
    const int q = z >> 1;

    const float* A;
    const float* B;
    float* C;
    int Kd, kStart, nChunks;
    if (MODE == 0) {
        A = which ? g_Prr : g_Pzr;  Kd = INdim;
        B = g_xr + (size_t)q * XT_STRIDE;
        C = (which ? g_Ar : g_Az) + (size_t)q * HB;
        kStart = 0;  nChunks = INdim / KCHUNK;           // 16
    } else {
        A = which ? g_Wrnd : g_Krnd;  Kd = Hdim;
        B = which ? g_m : g_r;
        C = (which ? g_G2p : g_G1p) + (size_t)q * HB;
        kStart = q * (Hdim / KSPLIT);
        nChunks = (Hdim / KSPLIT) / KCHUNK;              // 8
    }
    const int m0 = mb * 128;
    const int n0 = nb * 64;

    float* const sA[2] = { sm, sm + SA_FLOATS };
    float* const sB[2] = { sm + 2 * SA_FLOATS, sm + 2 * SA_FLOATS + SB_FLOATS };
    const uint32_t aBase[2] = { s2u(sA[0]), s2u(sA[1]) };
    const uint32_t bBase[2] = { s2u(sB[0]), s2u(sB[1]) };

    auto issue = [&](int c, int s) {
        const int kc = kStart + c * KCHUNK;
        // A tile: 128 x 32 = 1024 float4, 4 per thread
#pragma unroll
        for (int i = 0; i < 4; ++i) {
            const int e = i * 256 + tid, r = e >> 3, f4 = e & 7;
            cp_async16(aBase[s] + (uint32_t)(r * A_LD + f4 * 4) * 4,
                       A + (size_t)(m0 + r) * Kd + kc + f4 * 4);
        }
        // B tile: 32 x 64 = 512 float4, 2 per thread
#pragma unroll
        for (int i = 0; i < 2; ++i) {
            const int e = i * 256 + tid, r = e >> 4, f4 = e & 15;
            cp_async16(bBase[s] + (uint32_t)(r * B_LD + f4 * 4) * 4,
                       B + (size_t)(kc + r) * Bdim + n0 + f4 * 4);
        }
        cp_commit();
    };

    wmma::fragment<wmma::accumulator, 16, 16, 8, float> acc[2][2];
#pragma unroll
    for (int i = 0; i < 2; ++i)
#pragma unroll
        for (int j = 0; j < 2; ++j) wmma::fill_fragment(acc[i][j], 0.0f);

    issue(0, 0);
    for (int c = 0; c < nChunks; ++c) {
        if (c + 1 < nChunks) { issue(c + 1, (c + 1) & 1); cp_wait<1>(); }
        else                 { cp_wait<0>(); }
        __syncthreads();
        const float* cA = sA[c & 1];
        const float* cB = sB[c & 1];
#pragma unroll
        for (int ks = 0; ks < KCHUNK / 8; ++ks) {
            wmma::fragment<wmma::matrix_a, 16, 16, 8, wmma::precision::tf32,
                           wmma::row_major> af[2];
            wmma::fragment<wmma::matrix_b, 16, 16, 8, wmma::precision::tf32,
                           wmma::row_major> bf[2];
#pragma unroll
            for (int i = 0; i < 2; ++i)
                wmma::load_matrix_sync(af[i],
                    cA + (wm * 32 + i * 16) * A_LD + ks * 8, A_LD);
#pragma unroll
            for (int j = 0; j < 2; ++j)
                wmma::load_matrix_sync(bf[j],
                    cB + (ks * 8) * B_LD + wn * 32 + j * 16, B_LD);
#pragma unroll
            for (int i = 0; i < 2; ++i)
#pragma unroll
                for (int j = 0; j < 2; ++j)
                    wmma::mma_sync(acc[i][j], af[i], bf[j], acc[i][j]);
        }
        __syncthreads();
    }

    const int row = m0 + wm * 32;
    const int col = n0 + wn * 32;
#pragma unroll
    for (int i = 0; i < 2; ++i)
#pragma unroll
        for (int j = 0; j < 2; ++j)
            wmma::store_matrix_sync(C + (size_t)(row + i * 16) * Bdim + col + j * 16,
                                    acc[i][j], Bdim, wmma::mem_row_major);
}

// ---------------- elementwise step, float4-wide --------------------------
__global__ __launch_bounds__(256) void step_elem(
    const float* __restrict__ c_x, const float* __restrict__ c_u,
    const float* __restrict__ c_U, const float* __restrict__ gz,
    const float* __restrict__ br, int t)
{
    const int i4 = blockIdx.x * 256 + threadIdx.x;  // 0..65535
    const int idx = i4 * 4;
    const int h = idx >> 8;  // same h for all 4 lanes (B = 256)

    float v[4];
    *(float4*)v = *(const float4*)&g_v[idx];

    if (t > 0) {
        const size_t off = (size_t)(t - 1) * HB + idx;
        float s1[4], s2[4], az[4], ar[4], tmp[4];
        *(float4*)s1 = *(const float4*)&g_G1p[idx];
        *(float4*)s2 = *(const float4*)&g_G2p[idx];
#pragma unroll
        for (int p = 1; p < KSPLIT; ++p) {
            *(float4*)tmp = *(const float4*)&g_G1p[(size_t)p * HB + idx];
#pragma unroll
            for (int e = 0; e < 4; ++e) s1[e] += tmp[e];
            *(float4*)tmp = *(const float4*)&g_G2p[(size_t)p * HB + idx];
#pragma unroll
            for (int e = 0; e < 4; ++e) s2[e] += tmp[e];
        }
        *(float4*)az = *(const float4*)&g_Az[off];
        *(float4*)ar = *(const float4*)&g_Ar[off];
        const float gzh = gz[h], brh = br[h];
#pragma unroll
        for (int e = 0; e < 4; ++e) {
            float zt = 0.1f * sigm(s1[e] + az[e] + gzh);
            v[e] = (1.0f - zt) * v[e] + 0.1f * (s2[e] + ar[e] + brh);
        }
        *(float4*)&g_v[idx] = *(float4*)v;
        *(float4*)&g_Az[off] = *(float4*)v;  // stage v for final transpose
    }
    if (t < Tdim) {
        const float zx = 0.001f + 0.099f * sigm(c_x[h]);
        const float zu = 0.001f + 0.099f * sigm(c_u[h]);
        const float Uc = 0.9f * sigm(c_U[h]);
        float X[4], U[4], rr[4], mm[4];
        *(float4*)X = *(const float4*)&g_X[idx];
        *(float4*)U = *(const float4*)&g_U[idx];
#pragma unroll
        for (int e = 0; e < 4; ++e) {
            const float r = sigm(v[e]);
            float Xn = zx + (1.0f - zx) * X[e] - U[e] * X[e] * r;
            float Un = Uc * zu + (1.0f - zu) * U[e] + Uc * (1.0f - U[e]) * r;
            Un = fminf(fmaxf(Un, Uc), 1.0f);
            X[e] = Xn;
            U[e] = Un;
            rr[e] = totf32(r);
            mm[e] = totf32(Un * Xn * r);
        }
        *(float4*)&g_X[idx] = *(float4*)X;
        *(float4*)&g_U[idx] = *(float4*)U;
        *(float4*)&g_r[idx] = *(float4*)rr;
        *(float4*)&g_m[idx] = *(float4*)mm;
    }
}

// ---------------- final transpose: g_Az[t][h][b] -> out[t][b][h] ---------
__global__ __launch_bounds__(256) void transpose_out(float* __restrict__ out) {
    __shared__ float tile[32][33];
    const int t = blockIdx.z;
    const int h0 = blockIdx.y * 32;
    const int b0 = blockIdx.x * 32;
    const float* src = g_Az + (size_t)t * HB;
    float* dst = out + (size_t)t * HB;
    const int lx = threadIdx.x, ly = threadIdx.y;
#pragma unroll
    for (int i = 0; i < 32; i += 8)
        tile[ly + i][lx] = src[(size_t)(h0 + ly + i) * Bdim + b0 + lx];
    __syncthreads();
#pragma unroll
    for (int i = 0; i < 32; i += 8)
        dst[(size_t)(b0 + ly + i) * Hdim + h0 + lx] = tile[lx][ly + i];
}

// ---------------- launch ----------------
extern "C" void kernel_launch(void* const* d_in, const int* in_sizes, int n_in,
                              void* d_out, int out_size)
{
    const float* x   = (const float*)d_in[0];  // (T, IN, B)
    const float* c_x = (const float*)d_in[1];
    const float* c_u = (const float*)d_in[2];
    const float* c_U = (const float*)d_in[3];
    const float* w_r = (const float*)d_in[4];  // (H,H)
    const float* p_r = (const float*)d_in[5];  // (H,IN)
    const float* b_r = (const float*)d_in[6];
    const float* g_z = (const float*)d_in[7];
    const float* Km  = (const float*)d_in[8];  // (H,H)
    const float* p_z = (const float*)d_in[9];  // (H,IN)
    float* out = (float*)d_out;                // (T, B, H)

    cudaFuncSetAttribute(gemm_smem<0>,
                         cudaFuncAttributeMaxDynamicSharedMemorySize, SMEM_BYTES);
    cudaFuncSetAttribute(gemm_smem<1>,
                         cudaFuncAttributeMaxDynamicSharedMemorySize, SMEM_BYTES);

    init_state_kernel<<<HB / 256, 256>>>();

    round_copy<<<(Hdim * Hdim / 4) / 256, 256>>>(Km, 0);
    round_copy<<<(Hdim * Hdim / 4) / 256, 256>>>(w_r, 1);
    round_copy<<<(Hdim * INdim / 4) / 256, 256>>>(p_z, 2);
    round_copy<<<(Hdim * INdim / 4) / 256, 256>>>(p_r, 3);
    round_copy<<<(int)(((size_t)Tdim * XT_STRIDE / 4) / 256), 256>>>(x, 4);

    // input projections: Az[t] = p_z@x_t, Ar[t] = p_r@x_t (biases in step_elem)
    gemm_smem<0><<<dim3(8, 4, 2 * Tdim), 256, SMEM_BYTES>>>();

    // recurrence: G1 = K@r, G2 = w_r@m, K-split=4
    for (int t = 0; t < Tdim; ++t) {
        step_elem<<<HB / 1024, 256>>>(c_x, c_u, c_U, g_z, b_r, t);
        gemm_smem<1><<<dim3(8, 4, 2 * KSPLIT), 256, SMEM_BYTES>>>();
    }
    step_elem<<<HB / 1024, 256>>>(c_x, c_u, c_U, g_z, b_r, Tdim);

    transpose_out<<<dim3(Bdim / 32, Hdim / 32, Tdim), dim3(32, 8)>>>(out);
}

// round 8
// speedup vs baseline: 2.1344x; 1.5964x over previous
#include <cuda_runtime.h>
#include <mma.h>
#include <cstdint>
#include <math.h>

using namespace nvcuda;

#define Hdim 1024
#define INdim 512
#define Bdim 256
#define Tdim 256
#define HB (Hdim * Bdim)          // 262144 elements
#define KSPLIT 4
#define XT_STRIDE (INdim * Bdim)  // 131072 floats per timestep of x
#define NBLOCKS 256

#define KCHUNK 32
#define A_LD 36                   // 32 + 4 pad floats
#define B_LD 68                   // 64 + 4 pad floats
#define SA_FLOATS (128 * A_LD)    // 4608
#define SB_FLOATS (KCHUNK * B_LD) // 2176
#define SMEM_BYTES (2 * (SA_FLOATS + SB_FLOATS) * 4)  // 54272

// ---------------- device scratch (no cudaMalloc allowed) ----------------
// ONLY referenced in device code (host-arg binding of __device__ globals
// silently resolves to the host shadow on GB300 ATS — the R4/R5 bug).
__device__ __align__(1024) float g_Az[(size_t)Tdim * HB];   // 256 MiB
__device__ __align__(1024) float g_Ar[(size_t)Tdim * HB];   // 256 MiB
__device__ __align__(1024) float g_Krnd[Hdim * Hdim];
__device__ __align__(1024) float g_Wrnd[Hdim * Hdim];
__device__ __align__(1024) float g_Pzr[Hdim * INdim];
__device__ __align__(1024) float g_Prr[Hdim * INdim];
__device__ __align__(1024) float g_r[HB];
__device__ __align__(1024) float g_m[HB];
__device__ __align__(1024) float g_G1p[KSPLIT * HB];
__device__ __align__(1024) float g_G2p[KSPLIT * HB];
__device__ unsigned long long g_barrier;  // monotonic, never reset

// ---------------- helpers ----------------
__device__ __forceinline__ float sigm(float x) {
    return 1.0f / (1.0f + __expf(-x));
}
__device__ __forceinline__ float totf32(float x) {
    uint32_t o;
    asm("cvt.rna.tf32.f32 %0, %1;" : "=r"(o) : "f"(x));
    return __uint_as_float(o);
}
__device__ __forceinline__ uint32_t s2u(const void* p) {
    return (uint32_t)__cvta_generic_to_shared(p);
}
__device__ __forceinline__ void cp_async16_ca(uint32_t saddr, const void* g) {
    asm volatile("cp.async.ca.shared.global [%0], [%1], 16;"
                 :: "r"(saddr), "l"(g));
}
__device__ __forceinline__ void cp_async16_cg(uint32_t saddr, const void* g) {
    asm volatile("cp.async.cg.shared.global [%0], [%1], 16;"
                 :: "r"(saddr), "l"(g));
}
__device__ __forceinline__ void cp_commit() {
    asm volatile("cp.async.commit_group;" ::: "memory");
}
template <int N>
__device__ __forceinline__ void cp_wait() {
    asm volatile("cp.async.wait_group %0;" :: "n"(N) : "memory");
}

// Grid-wide barrier: monotonic 64-bit counter, generation = count/NBLOCKS.
__device__ __forceinline__ void grid_sync() {
    __syncthreads();
    if (threadIdx.x == 0) {
        __threadfence();
        unsigned long long old = atomicAdd(&g_barrier, 1ull);
        unsigned long long target = (old / NBLOCKS + 1) * NBLOCKS;
        unsigned long long cur;
        do {
            asm volatile("ld.acquire.gpu.global.u64 %0, [%1];"
                         : "=l"(cur) : "l"(&g_barrier));
        } while (cur < target);
    }
    __syncthreads();
}

// ---------------- tf32 rounding of weight matrices -----------------------
__global__ __launch_bounds__(256) void round_copy(const float* __restrict__ src,
                                                  int which) {
    float* dst = which == 0 ? g_Krnd : which == 1 ? g_Wrnd
               : which == 2 ? g_Pzr  : g_Prr;
    const size_t i = (size_t)blockIdx.x * 256 + threadIdx.x;
    float4 v = ((const float4*)src)[i];
    v.x = totf32(v.x); v.y = totf32(v.y);
    v.z = totf32(v.z); v.w = totf32(v.w);
    ((float4*)dst)[i] = v;
}

// ---------------- projection GEMM: Az/Ar[t] = P @ x_t --------------------
// grid (8, 4, 2*Tdim); which = z&1, q = z>>1 (timestep). x rounded to tf32
// in smem after cp.async (raw harness x used directly).
__global__ __launch_bounds__(256) void proj_gemm(const float* __restrict__ x) {
    extern __shared__ float sm[];
    const int tid = threadIdx.x;
    const int warp = tid >> 5;
    const int wm = warp >> 1, wn = warp & 1;
    const int mb = blockIdx.x, nb = blockIdx.y;
    const int which = blockIdx.z & 1, q = blockIdx.z >> 1;

    const float* A = which ? g_Prr : g_Pzr;
    const float* B = x + (size_t)q * XT_STRIDE;
    float* C = (which ? g_Ar : g_Az) + (size_t)q * HB;
    const int Kd = INdim, nChunks = INdim / KCHUNK;  // 16
    const int m0 = mb * 128, n0 = nb * 64;

    float* const sA[2] = { sm, sm + SA_FLOATS };
    float* const sB[2] = { sm + 2 * SA_FLOATS, sm + 2 * SA_FLOATS + SB_FLOATS };
    const uint32_t aB[2] = { s2u(sA[0]), s2u(sA[1]) };
    const uint32_t bB[2] = { s2u(sB[0]), s2u(sB[1]) };

    auto issue = [&](int c, int s) {
        const int kc = c * KCHUNK;
#pragma unroll
        for (int i = 0; i < 4; ++i) {
            const int e = i * 256 + tid, r = e >> 3, f4 = e & 7;
            cp_async16_ca(aB[s] + (uint32_t)(r * A_LD + f4 * 4) * 4,
                          A + (size_t)(m0 + r) * Kd + kc + f4 * 4);
        }
#pragma unroll
        for (int i = 0; i < 2; ++i) {
            const int e = i * 256 + tid, r = e >> 4, f4 = e & 15;
            cp_async16_ca(bB[s] + (uint32_t)(r * B_LD + f4 * 4) * 4,
                          B + (size_t)(kc + r) * Bdim + n0 + f4 * 4);
        }
        cp_commit();
    };

    wmma::fragment<wmma::accumulator, 16, 16, 8, float> acc[2][2];
#pragma unroll
    for (int i = 0; i < 2; ++i)
#pragma unroll
        for (int j = 0; j < 2; ++j) wmma::fill_fragment(acc[i][j], 0.0f);

    issue(0, 0);
    for (int c = 0; c < nChunks; ++c) {
        if (c + 1 < nChunks) { issue(c + 1, (c + 1) & 1); cp_wait<1>(); }
        else                 { cp_wait<0>(); }
        __syncthreads();
        float* cB = sB[c & 1];
        // round the x tile to tf32 in place (weights pre-rounded)
        for (int i = tid; i < SB_FLOATS; i += 256) cB[i] = totf32(cB[i]);
        __syncthreads();
        const float* cA = sA[c & 1];
#pragma unroll
        for (int ks = 0; ks < KCHUNK / 8; ++ks) {
            wmma::fragment<wmma::matrix_a, 16, 16, 8, wmma::precision::tf32,
                           wmma::row_major> af[2];
            wmma::fragment<wmma::matrix_b, 16, 16, 8, wmma::precision::tf32,
                           wmma::row_major> bf[2];
#pragma unroll
            for (int i = 0; i < 2; ++i)
                wmma::load_matrix_sync(af[i],
                    cA + (wm * 32 + i * 16) * A_LD + ks * 8, A_LD);
#pragma unroll
            for (int j = 0; j < 2; ++j)
                wmma::load_matrix_sync(bf[j],
                    cB + (ks * 8) * B_LD + wn * 32 + j * 16, B_LD);
#pragma unroll
            for (int i = 0; i < 2; ++i)
#pragma unroll
                for (int j = 0; j < 2; ++j)
                    wmma::mma_sync(acc[i][j], af[i], bf[j], acc[i][j]);
        }
        __syncthreads();
    }
    const int row = m0 + wm * 32, col = n0 + wn * 32;
#pragma unroll
    for (int i = 0; i < 2; ++i)
#pragma unroll
        for (int j = 0; j < 2; ++j)
            wmma::store_matrix_sync(C + (size_t)(row + i * 16) * Bdim + col + j * 16,
                                    acc[i][j], Bdim, wmma::mem_row_major);
}

// ---------------- persistent recurrence kernel ---------------------------
// 256 blocks x 256 threads, all co-resident (<=128 regs via launch_bounds,
// 54.3KB smem -> >=2 blocks/SM -> capacity 296 >= 256).
// Each thread owns 4 state elements (v, X, U) in REGISTERS for all 256 steps.
// Per step: elem phase -> grid_sync -> gemm phase (tile per block) -> grid_sync.
__global__ __launch_bounds__(256, 2) void recurrence(
    const float* __restrict__ c_x, const float* __restrict__ c_u,
    const float* __restrict__ c_U, const float* __restrict__ gz,
    const float* __restrict__ br)
{
    extern __shared__ float sm[];
    const int tid = threadIdx.x;
    const int bid = blockIdx.x;

    // ----- elem identity: 4 consecutive elements of [H][B] -----
    const int idx = (bid * 256 + tid) * 4;
    const int h = idx >> 8;
    const float zx = 0.001f + 0.099f * sigm(c_x[h]);
    const float zu = 0.001f + 0.099f * sigm(c_u[h]);
    const float Uc = 0.9f * sigm(c_U[h]);
    const float gzh = gz[h], brh = br[h];
    float v[4] = {0.f, 0.f, 0.f, 0.f};
    float X[4] = {1.f, 1.f, 1.f, 1.f};
    float U[4] = {0.9f, 0.9f, 0.9f, 0.9f};

    // ----- gemm identity: (mb, nb, which, q) tile -----
    const int which = bid & 1;
    const int q = (bid >> 1) & 3;
    const int nb = (bid >> 3) & 3;
    const int mb = bid >> 5;
    const int warp = tid >> 5;
    const int wm = warp >> 1, wn = warp & 1;
    const float* Ag = which ? g_Wrnd : g_Krnd;
    const float* Bg = which ? g_m : g_r;
    float* Cg = (which ? g_G2p : g_G1p) + (size_t)q * HB;
    const int kStart = q * (Hdim / KSPLIT);
    const int m0 = mb * 128, n0 = nb * 64;

    float* const sA[2] = { sm, sm + SA_FLOATS };
    float* const sB[2] = { sm + 2 * SA_FLOATS, sm + 2 * SA_FLOATS + SB_FLOATS };
    const uint32_t aB[2] = { s2u(sA[0]), s2u(sA[1]) };
    const uint32_t bB[2] = { s2u(sB[0]), s2u(sB[1]) };

    for (int t = 0; t < Tdim; ++t) {
        // ===== elem phase =====
        if (t > 0) {
            const size_t off = (size_t)(t - 1) * HB + idx;
            float s1[4], s2[4], tmp[4];
            *(float4*)s1 = __ldcg((const float4*)&g_G1p[idx]);
            *(float4*)s2 = __ldcg((const float4*)&g_G2p[idx]);
#pragma unroll
            for (int p = 1; p < KSPLIT; ++p) {
                *(float4*)tmp = __ldcg((const float4*)&g_G1p[(size_t)p * HB + idx]);
#pragma unroll
                for (int e = 0; e < 4; ++e) s1[e] += tmp[e];
                *(float4*)tmp = __ldcg((const float4*)&g_G2p[(size_t)p * HB + idx]);
#pragma unroll
                for (int e = 0; e < 4; ++e) s2[e] += tmp[e];
            }
            float az[4], ar[4];
            *(float4*)az = *(const float4*)&g_Az[off];
            *(float4*)ar = *(const float4*)&g_Ar[off];
#pragma unroll
            for (int e = 0; e < 4; ++e) {
                float zt = 0.1f * sigm(s1[e] + az[e] + gzh);
                v[e] = (1.0f - zt) * v[e] + 0.1f * (s2[e] + ar[e] + brh);
            }
            *(float4*)&g_Az[off] = *(float4*)v;  // stage v_{t-1} for transpose
        }
        {
            float rr[4], mm[4];
#pragma unroll
            for (int e = 0; e < 4; ++e) {
                const float r = sigm(v[e]);
                float Xn = zx + (1.0f - zx) * X[e] - U[e] * X[e] * r;
                float Un = Uc * zu + (1.0f - zu) * U[e] + Uc * (1.0f - U[e]) * r;
                Un = fminf(fmaxf(Un, Uc), 1.0f);
                X[e] = Xn;
                U[e] = Un;
                rr[e] = totf32(r);
                mm[e] = totf32(Un * Xn * r);
            }
            *(float4*)&g_r[idx] = *(float4*)rr;
            *(float4*)&g_m[idx] = *(float4*)mm;
        }
        grid_sync();

        // ===== gemm phase: C_partial = A[m0:,kStart:+256] @ B[kStart:+256,n0:] =====
        {
            auto issue = [&](int c, int s) {
                const int kc = kStart + c * KCHUNK;
#pragma unroll
                for (int i = 0; i < 4; ++i) {
                    const int e = i * 256 + tid, r = e >> 3, f4 = e & 7;
                    cp_async16_ca(aB[s] + (uint32_t)(r * A_LD + f4 * 4) * 4,
                                  Ag + (size_t)(m0 + r) * Hdim + kc + f4 * 4);
                }
                // B must bypass L1: rewritten every step by other SMs
#pragma unroll
                for (int i = 0; i < 2; ++i) {
                    const int e = i * 256 + tid, r = e >> 4, f4 = e & 15;
                    cp_async16_cg(bB[s] + (uint32_t)(r * B_LD + f4 * 4) * 4,
                                  Bg + (size_t)(kc + r) * Bdim + n0 + f4 * 4);
                }
                cp_commit();
            };

            wmma::fragment<wmma::accumulator, 16, 16, 8, float> acc[2][2];
#pragma unroll
            for (int i = 0; i < 2; ++i)
#pragma unroll
                for (int j = 0; j < 2; ++j) wmma::fill_fragment(acc[i][j], 0.0f);

            const int nChunks = (Hdim / KSPLIT) / KCHUNK;  // 8
            issue(0, 0);
            for (int c = 0; c < nChunks; ++c) {
                if (c + 1 < nChunks) { issue(c + 1, (c + 1) & 1); cp_wait<1>(); }
                else                 { cp_wait<0>(); }
                __syncthreads();
                const float* cA = sA[c & 1];
                const float* cB = sB[c & 1];
#pragma unroll
                for (int ks = 0; ks < KCHUNK / 8; ++ks) {
                    wmma::fragment<wmma::matrix_a, 16, 16, 8,
                                   wmma::precision::tf32, wmma::row_major> af[2];
                    wmma::fragment<wmma::matrix_b, 16, 16, 8,
                                   wmma::precision::tf32, wmma::row_major> bf[2];
#pragma unroll
                    for (int i = 0; i < 2; ++i)
                        wmma::load_matrix_sync(af[i],
                            cA + (wm * 32 + i * 16) * A_LD + ks * 8, A_LD);
#pragma unroll
                    for (int j = 0; j < 2; ++j)
                        wmma::load_matrix_sync(bf[j],
                            cB + (ks * 8) * B_LD + wn * 32 + j * 16, B_LD);
#pragma unroll
                    for (int i = 0; i < 2; ++i)
#pragma unroll
                        for (int j = 0; j < 2; ++j)
                            wmma::mma_sync(acc[i][j], af[i], bf[j], acc[i][j]);
                }
                __syncthreads();
            }
            const int row = m0 + wm * 32, col = n0 + wn * 32;
#pragma unroll
            for (int i = 0; i < 2; ++i)
#pragma unroll
                for (int j = 0; j < 2; ++j)
                    wmma::store_matrix_sync(
                        Cg + (size_t)(row + i * 16) * Bdim + col + j * 16,
                        acc[i][j], Bdim, wmma::mem_row_major);
        }
        grid_sync();
    }

    // ===== final epilogue: t = Tdim =====
    {
        const size_t off = (size_t)(Tdim - 1) * HB + idx;
        float s1[4], s2[4], tmp[4];
        *(float4*)s1 = __ldcg((const float4*)&g_G1p[idx]);
        *(float4*)s2 = __ldcg((const float4*)&g_G2p[idx]);
#pragma unroll
        for (int p = 1; p < KSPLIT; ++p) {
            *(float4*)tmp = __ldcg((const float4*)&g_G1p[(size_t)p * HB + idx]);
#pragma unroll
            for (int e = 0; e < 4; ++e) s1[e] += tmp[e];
            *(float4*)tmp = __ldcg((const float4*)&g_G2p[(size_t)p * HB + idx]);
#pragma unroll
            for (int e = 0; e < 4; ++e) s2[e] += tmp[e];
        }
        float az[4], ar[4];
        *(float4*)az = *(const float4*)&g_Az[off];
        *(float4*)ar = *(const float4*)&g_Ar[off];
#pragma unroll
        for (int e = 0; e < 4; ++e) {
            float zt = 0.1f * sigm(s1[e] + az[e] + gzh);
            v[e] = (1.0f - zt) * v[e] + 0.1f * (s2[e] + ar[e] + brh);
        }
        *(float4*)&g_Az[off] = *(float4*)v;
    }
}

// ---------------- final transpose: g_Az[t][h][b] -> out[t][b][h] ---------
__global__ __launch_bounds__(256) void transpose_out(float* __restrict__ out) {
    __shared__ float tile[32][33];
    const int t = blockIdx.z;
    const int h0 = blockIdx.y * 32;
    const int b0 = blockIdx.x * 32;
    const float* src = g_Az + (size_t)t * HB;
    float* dst = out + (size_t)t * HB;
    const int lx = threadIdx.x, ly = threadIdx.y;
#pragma unroll
    for (int i = 0; i < 32; i += 8)
        tile[ly + i][lx] = src[(size_t)(h0 + ly + i) * Bdim + b0 + lx];
    __syncthreads();
#pragma unroll
    for (int i = 0; i < 32; i += 8)
        dst[(size_t)(b0 + ly + i) * Hdim + h0 + lx] = tile[lx][ly + i];
}

// ---------------- launch ----------------
extern "C" void kernel_launch(void* const* d_in, const int* in_sizes, int n_in,
                              void* d_out, int out_size)
{
    const float* x   = (const float*)d_in[0];  // (T, IN, B)
    const float* c_x = (const float*)d_in[1];
    const float* c_u = (const float*)d_in[2];
    const float* c_U = (const float*)d_in[3];
    const float* w_r = (const float*)d_in[4];  // (H,H)
    const float* p_r = (const float*)d_in[5];  // (H,IN)
    const float* b_r = (const float*)d_in[6];
    const float* g_z = (const float*)d_in[7];
    const float* Km  = (const float*)d_in[8];  // (H,H)
    const float* p_z = (const float*)d_in[9];  // (H,IN)
    float* out = (float*)d_out;                // (T, B, H)

    cudaFuncSetAttribute(proj_gemm,
                         cudaFuncAttributeMaxDynamicSharedMemorySize, SMEM_BYTES);
    cudaFuncSetAttribute(recurrence,
                         cudaFuncAttributeMaxDynamicSharedMemorySize, SMEM_BYTES);

    // launches 1-4: weight rounding
    round_copy<<<(Hdim * Hdim / 4) / 256, 256>>>(Km, 0);
    round_copy<<<(Hdim * Hdim / 4) / 256, 256>>>(w_r, 1);
    round_copy<<<(Hdim * INdim / 4) / 256, 256>>>(p_z, 2);
    round_copy<<<(Hdim * INdim / 4) / 256, 256>>>(p_r, 3);
    // launch 5: input projections (x rounded in smem)
    proj_gemm<<<dim3(8, 4, 2 * Tdim), 256, SMEM_BYTES>>>(x);
    // launch 6 (ncu capture slot): the whole recurrence
    recurrence<<<NBLOCKS, 256, SMEM_BYTES>>>(c_x, c_u, c_U, g_z, b_r);
    // launch 7: output transpose
    transpose_out<<<dim3(Bdim / 32, Hdim / 32, Tdim), dim3(32, 8)>>>(out);
}

// round 9
// speedup vs baseline: 5.3840x; 2.5225x over previous
#include <cuda_runtime.h>
#include <cuda_fp16.h>
#include <mma.h>
#include <cstdint>
#include <math.h>

using namespace nvcuda;

#define Hdim 1024
#define INdim 512
#define Bdim 256
#define Tdim 256
#define HB (Hdim * Bdim)          // 262144 elements
#define KSPLIT 4
#define XT_STRIDE (INdim * Bdim)  // 131072 elements per timestep of x
#define NBLOCKS 256

#define KCHUNK 32
#define A_LD 40                   // halfs: 32 + 8 pad; 80B rows, 16B-aligned
#define B_LD 72                   // halfs: 64 + 8 pad; 144B rows, 16B-aligned
#define SA_HALFS (128 * A_LD)     // 5120
#define SB_HALFS (KCHUNK * B_LD)  // 2304
#define SMEM_BYTES (2 * (SA_HALFS + SB_HALFS) * 2)  // 29696

// ---------------- device scratch (no cudaMalloc allowed) ----------------
// ONLY referenced in device code (host-arg binding of __device__ globals
// silently resolves to the host shadow on GB300 ATS — the R4/R5 bug).
__device__ __align__(1024) float g_Az[(size_t)Tdim * HB];   // 256 MiB
__device__ __align__(1024) float g_Ar[(size_t)Tdim * HB];   // 256 MiB
__device__ __align__(1024) __half g_xh[(size_t)Tdim * XT_STRIDE];  // 64 MiB
__device__ __align__(1024) __half g_Kh[Hdim * Hdim];
__device__ __align__(1024) __half g_Wh[Hdim * Hdim];
__device__ __align__(1024) __half g_Pzh[Hdim * INdim];
__device__ __align__(1024) __half g_Prh[Hdim * INdim];
__device__ __align__(1024) __half g_rh[HB];
__device__ __align__(1024) __half g_mh[HB];
__device__ __align__(1024) float g_G1p[KSPLIT * HB];
__device__ __align__(1024) float g_G2p[KSPLIT * HB];
__device__ unsigned long long g_barrier;  // monotonic, never reset

// ---------------- helpers ----------------
__device__ __forceinline__ float sigm(float x) {
    return 1.0f / (1.0f + __expf(-x));
}
__device__ __forceinline__ uint32_t s2u(const void* p) {
    return (uint32_t)__cvta_generic_to_shared(p);
}
__device__ __forceinline__ void cp_async16_ca(uint32_t saddr, const void* g) {
    asm volatile("cp.async.ca.shared.global [%0], [%1], 16;"
                 :: "r"(saddr), "l"(g));
}
__device__ __forceinline__ void cp_async16_cg(uint32_t saddr, const void* g) {
    asm volatile("cp.async.cg.shared.global [%0], [%1], 16;"
                 :: "r"(saddr), "l"(g));
}
__device__ __forceinline__ void cp_commit() {
    asm volatile("cp.async.commit_group;" ::: "memory");
}
template <int N>
__device__ __forceinline__ void cp_wait() {
    asm volatile("cp.async.wait_group %0;" :: "n"(N) : "memory");
}

// Grid-wide barrier: monotonic 64-bit counter, generation = count/NBLOCKS.
__device__ __forceinline__ void grid_sync() {
    __syncthreads();
    if (threadIdx.x == 0) {
        __threadfence();
        unsigned long long old = atomicAdd(&g_barrier, 1ull);
        unsigned long long target = (old / NBLOCKS + 1) * NBLOCKS;
        unsigned long long cur;
        do {
            asm volatile("ld.acquire.gpu.global.u64 %0, [%1];"
                         : "=l"(cur) : "l"(&g_barrier));
        } while (cur < target);
    }
    __syncthreads();
}

// ---------------- weight conversion: fp32 -> fp16 (one launch) -----------
// layout: [K 1M][W 1M][Pz 0.5M][Pr 0.5M] = 3M elements, 4 per thread.
__global__ __launch_bounds__(256) void conv_weights(
    const float* __restrict__ Km, const float* __restrict__ Wr,
    const float* __restrict__ Pz, const float* __restrict__ Pr)
{
    const size_t i = ((size_t)blockIdx.x * 256 + threadIdx.x) * 4;
    const float* src;
    __half* dst;
    size_t off;
    if (i < (size_t)Hdim * Hdim) { src = Km; dst = g_Kh; off = i; }
    else if (i < 2ull * Hdim * Hdim) {
        src = Wr; dst = g_Wh; off = i - (size_t)Hdim * Hdim;
    } else if (i < 2ull * Hdim * Hdim + (size_t)Hdim * INdim) {
        src = Pz; dst = g_Pzh; off = i - 2ull * Hdim * Hdim;
    } else {
        src = Pr; dst = g_Prh; off = i - 2ull * Hdim * Hdim - (size_t)Hdim * INdim;
    }
    float4 v = *(const float4*)&src[off];
    __half h[4] = { __float2half_rn(v.x), __float2half_rn(v.y),
                    __float2half_rn(v.z), __float2half_rn(v.w) };
    *(uint2*)&dst[off] = *(uint2*)h;
}

// ---------------- x conversion: fp32 -> fp16 ------------------------------
__global__ __launch_bounds__(256) void conv_x(const float* __restrict__ x) {
    const size_t i = ((size_t)blockIdx.x * 256 + threadIdx.x) * 4;
    float4 v = *(const float4*)&x[i];
    __half h[4] = { __float2half_rn(v.x), __float2half_rn(v.y),
                    __float2half_rn(v.z), __float2half_rn(v.w) };
    *(uint2*)&g_xh[i] = *(uint2*)h;
}

// ---------------- shared GEMM tile core (fp16 operands, fp32 acc) --------
// C[128x64] = A[128 x nChunks*32] @ B[.. x 64]; A ld=Kd halfs, B ld=256.
struct TileArgs {
    const __half* A; const __half* B; float* C;
    int Kd, kStart, nChunks, m0, n0;
};
template <bool BCG>
__device__ __forceinline__ void gemm_tile(const TileArgs& ta, __half* sm,
                                          int tid) {
    const int warp = tid >> 5;
    const int wm = warp >> 1, wn = warp & 1;
    __half* const sA[2] = { sm, sm + SA_HALFS };
    __half* const sB[2] = { sm + 2 * SA_HALFS, sm + 2 * SA_HALFS + SB_HALFS };
    const uint32_t aB[2] = { s2u(sA[0]), s2u(sA[1]) };
    const uint32_t bB[2] = { s2u(sB[0]), s2u(sB[1]) };

    auto issue = [&](int c, int s) {
        const int kc = ta.kStart + c * KCHUNK;
        // A tile: 128 x 32 halfs = 512 x 16B; 2 per thread
#pragma unroll
        for (int i = 0; i < 2; ++i) {
            const int e = i * 256 + tid, r = e >> 2, f8 = e & 3;
            cp_async16_ca(aB[s] + (uint32_t)(r * A_LD + f8 * 8) * 2,
                          ta.A + (size_t)(ta.m0 + r) * ta.Kd + kc + f8 * 8);
        }
        // B tile: 32 x 64 halfs = 256 x 16B; 1 per thread
        {
            const int r = tid >> 3, f8 = tid & 7;
            const __half* src = ta.B + (size_t)(kc + r) * Bdim + ta.n0 + f8 * 8;
            const uint32_t dst = bB[s] + (uint32_t)(r * B_LD + f8 * 8) * 2;
            if (BCG) cp_async16_cg(dst, src);  // bypass L1: rewritten per step
            else     cp_async16_ca(dst, src);
        }
        cp_commit();
    };

    wmma::fragment<wmma::accumulator, 16, 16, 16, float> acc[2][2];
#pragma unroll
    for (int i = 0; i < 2; ++i)
#pragma unroll
        for (int j = 0; j < 2; ++j) wmma::fill_fragment(acc[i][j], 0.0f);

    issue(0, 0);
    for (int c = 0; c < ta.nChunks; ++c) {
        if (c + 1 < ta.nChunks) { issue(c + 1, (c + 1) & 1); cp_wait<1>(); }
        else                    { cp_wait<0>(); }
        __syncthreads();
        const __half* cA = sA[c & 1];
        const __half* cB = sB[c & 1];
#pragma unroll
        for (int ks = 0; ks < KCHUNK / 16; ++ks) {
            wmma::fragment<wmma::matrix_a, 16, 16, 16, __half,
                           wmma::row_major> af[2];
            wmma::fragment<wmma::matrix_b, 16, 16, 16, __half,
                           wmma::row_major> bf[2];
#pragma unroll
            for (int i = 0; i < 2; ++i)
                wmma::load_matrix_sync(af[i],
                    cA + (wm * 32 + i * 16) * A_LD + ks * 16, A_LD);
#pragma unroll
            for (int j = 0; j < 2; ++j)
                wmma::load_matrix_sync(bf[j],
                    cB + (ks * 16) * B_LD + wn * 32 + j * 16, B_LD);
#pragma unroll
            for (int i = 0; i < 2; ++i)
#pragma unroll
                for (int j = 0; j < 2; ++j)
                    wmma::mma_sync(acc[i][j], af[i], bf[j], acc[i][j]);
        }
        __syncthreads();
    }
    const int row = ta.m0 + wm * 32, col = ta.n0 + wn * 32;
#pragma unroll
    for (int i = 0; i < 2; ++i)
#pragma unroll
        for (int j = 0; j < 2; ++j)
            wmma::store_matrix_sync(
                ta.C + (size_t)(row + i * 16) * Bdim + col + j * 16,
                acc[i][j], Bdim, wmma::mem_row_major);
}

// ---------------- projection GEMM: Az/Ar[t] = P @ x_t --------------------
__global__ __launch_bounds__(256, 2) void proj_gemm() {
    extern __shared__ __half smh[];
    const int which = blockIdx.z & 1, q = blockIdx.z >> 1;
    TileArgs ta;
    ta.A = which ? g_Prh : g_Pzh;
    ta.B = g_xh + (size_t)q * XT_STRIDE;
    ta.C = (which ? g_Ar : g_Az) + (size_t)q * HB;
    ta.Kd = INdim; ta.kStart = 0; ta.nChunks = INdim / KCHUNK;  // 16
    ta.m0 = blockIdx.x * 128; ta.n0 = blockIdx.y * 64;
    gemm_tile<false>(ta, smh, threadIdx.x);
}

// ---------------- persistent recurrence kernel ---------------------------
// 256 blocks x 256 threads, co-resident (smem 29.7KB -> 2 blocks/SM,
// regs <=128 via launch_bounds). State (v,X,U) in registers all 256 steps.
__global__ __launch_bounds__(256, 2) void recurrence(
    const float* __restrict__ c_x, const float* __restrict__ c_u,
    const float* __restrict__ c_U, const float* __restrict__ gz,
    const float* __restrict__ br)
{
    extern __shared__ __half smh[];
    const int tid = threadIdx.x;
    const int bid = blockIdx.x;

    // ----- elem identity: 4 consecutive elements of [H][B] -----
    const int idx = (bid * 256 + tid) * 4;
    const int h = idx >> 8;
    const float zx = 0.001f + 0.099f * sigm(c_x[h]);
    const float zu = 0.001f + 0.099f * sigm(c_u[h]);
    const float Uc = 0.9f * sigm(c_U[h]);
    const float gzh = gz[h], brh = br[h];
    float v[4] = {0.f, 0.f, 0.f, 0.f};
    float X[4] = {1.f, 1.f, 1.f, 1.f};
    float U[4] = {0.9f, 0.9f, 0.9f, 0.9f};

    // ----- gemm identity: (mb, nb, which, q) tile -----
    const int which = bid & 1;
    const int q = (bid >> 1) & 3;
    TileArgs ta;
    ta.A = which ? g_Wh : g_Kh;
    ta.B = which ? g_mh : g_rh;
    ta.C = (which ? g_G2p : g_G1p) + (size_t)q * HB;
    ta.Kd = Hdim;
    ta.kStart = q * (Hdim / KSPLIT);
    ta.nChunks = (Hdim / KSPLIT) / KCHUNK;  // 8
    ta.m0 = (bid >> 5) * 128;
    ta.n0 = ((bid >> 3) & 3) * 64;

    for (int t = 0; t < Tdim; ++t) {
        // ===== elem phase =====
        if (t > 0) {
            const size_t off = (size_t)(t - 1) * HB + idx;
            float s1[4], s2[4], tmp[4];
            *(float4*)s1 = __ldcg((const float4*)&g_G1p[idx]);
            *(float4*)s2 = __ldcg((const float4*)&g_G2p[idx]);
#pragma unroll
            for (int p = 1; p < KSPLIT; ++p) {
                *(float4*)tmp = __ldcg((const float4*)&g_G1p[(size_t)p * HB + idx]);
#pragma unroll
                for (int e = 0; e < 4; ++e) s1[e] += tmp[e];
                *(float4*)tmp = __ldcg((const float4*)&g_G2p[(size_t)p * HB + idx]);
#pragma unroll
                for (int e = 0; e < 4; ++e) s2[e] += tmp[e];
            }
            float az[4], ar[4];
            *(float4*)az = *(const float4*)&g_Az[off];
            *(float4*)ar = *(const float4*)&g_Ar[off];
#pragma unroll
            for (int e = 0; e < 4; ++e) {
                float zt = 0.1f * sigm(s1[e] + az[e] + gzh);
                v[e] = (1.0f - zt) * v[e] + 0.1f * (s2[e] + ar[e] + brh);
            }
            *(float4*)&g_Az[off] = *(float4*)v;  // stage v_{t-1} for transpose
        }
        {
            __half rr[4], mm[4];
#pragma unroll
            for (int e = 0; e < 4; ++e) {
                const float r = sigm(v[e]);
                float Xn = zx + (1.0f - zx) * X[e] - U[e] * X[e] * r;
                float Un = Uc * zu + (1.0f - zu) * U[e] + Uc * (1.0f - U[e]) * r;
                Un = fminf(fmaxf(Un, Uc), 1.0f);
                X[e] = Xn;
                U[e] = Un;
                rr[e] = __float2half_rn(r);
                mm[e] = __float2half_rn(Un * Xn * r);
            }
            *(uint2*)&g_rh[idx] = *(uint2*)rr;
            *(uint2*)&g_mh[idx] = *(uint2*)mm;
        }
        grid_sync();

        // ===== gemm phase =====
        gemm_tile<true>(ta, smh, tid);
        grid_sync();
    }

    // ===== final epilogue: t = Tdim =====
    {
        const size_t off = (size_t)(Tdim - 1) * HB + idx;
        float s1[4], s2[4], tmp[4];
        *(float4*)s1 = __ldcg((const float4*)&g_G1p[idx]);
        *(float4*)s2 = __ldcg((const float4*)&g_G2p[idx]);
#pragma unroll
        for (int p = 1; p < KSPLIT; ++p) {
            *(float4*)tmp = __ldcg((const float4*)&g_G1p[(size_t)p * HB + idx]);
#pragma unroll
            for (int e = 0; e < 4; ++e) s1[e] += tmp[e];
            *(float4*)tmp = __ldcg((const float4*)&g_G2p[(size_t)p * HB + idx]);
#pragma unroll
            for (int e = 0; e < 4; ++e) s2[e] += tmp[e];
        }
        float az[4], ar[4];
        *(float4*)az = *(const float4*)&g_Az[off];
        *(float4*)ar = *(const float4*)&g_Ar[off];
#pragma unroll
        for (int e = 0; e < 4; ++e) {
            float zt = 0.1f * sigm(s1[e] + az[e] + gzh);
            v[e] = (1.0f - zt) * v[e] + 0.1f * (s2[e] + ar[e] + brh);
        }
        *(float4*)&g_Az[off] = *(float4*)v;
    }
}

// ---------------- final transpose: g_Az[t][h][b] -> out[t][b][h] ---------
__global__ __launch_bounds__(256) void transpose_out(float* __restrict__ out) {
    __shared__ float tile[32][33];
    const int t = blockIdx.z;
    const int h0 = blockIdx.y * 32;
    const int b0 = blockIdx.x * 32;
    const float* src = g_Az + (size_t)t * HB;
    float* dst = out + (size_t)t * HB;
    const int lx = threadIdx.x, ly = threadIdx.y;
#pragma unroll
    for (int i = 0; i < 32; i += 8)
        tile[ly + i][lx] = src[(size_t)(h0 + ly + i) * Bdim + b0 + lx];
    __syncthreads();
#pragma unroll
    for (int i = 0; i < 32; i += 8)
        dst[(size_t)(b0 + ly + i) * Hdim + h0 + lx] = tile[lx][ly + i];
}

// ---------------- launch ----------------
extern "C" void kernel_launch(void* const* d_in, const int* in_sizes, int n_in,
                              void* d_out, int out_size)
{
    const float* x   = (const float*)d_in[0];  // (T, IN, B)
    const float* c_x = (const float*)d_in[1];
    const float* c_u = (const float*)d_in[2];
    const float* c_U = (const float*)d_in[3];
    const float* w_r = (const float*)d_in[4];  // (H,H)
    const float* p_r = (const float*)d_in[5];  // (H,IN)
    const float* b_r = (const float*)d_in[6];
    const float* g_z = (const float*)d_in[7];
    const float* Km  = (const float*)d_in[8];  // (H,H)
    const float* p_z = (const float*)d_in[9];  // (H,IN)
    float* out = (float*)d_out;                // (T, B, H)

    // 1: weight conversion (3M elements)
    conv_weights<<<(2 * Hdim * Hdim + 2 * Hdim * INdim) / 1024, 256>>>(
        Km, w_r, p_z, p_r);
    // 2: x conversion (32M elements)
    conv_x<<<(int)(((size_t)Tdim * XT_STRIDE) / 1024), 256>>>(x);
    // 3: input projections
    proj_gemm<<<dim3(8, 4, 2 * Tdim), 256, SMEM_BYTES>>>();
    // 4: the whole recurrence (persistent)
    recurrence<<<NBLOCKS, 256, SMEM_BYTES>>>(c_x, c_u, c_U, g_z, b_r);
    // 5: output transpose
    transpose_out<<<dim3(Bdim / 32, Hdim / 32, Tdim), dim3(32, 8)>>>(out);
}

// round 10
// speedup vs baseline: 5.5054x; 1.0225x over previous
#include <cuda_runtime.h>
#include <cuda_fp16.h>
#include <mma.h>
#include <cstdint>
#include <math.h>

using namespace nvcuda;

#define Hdim 1024
#define INdim 512
#define Bdim 256
#define Tdim 256
#define HB (Hdim * Bdim)          // 262144 elements
#define KSPLIT 2
#define XT_STRIDE (INdim * Bdim)
#define NBLOCKS 128
#define KCHUNK 32

// recurrence smem: persistent A slice 128x512 halfs + B double buffer
#define A_LDR 520                 // 512 + 8 pad halfs; 1040B row (65x16B, odd)
#define SA_R (128 * A_LDR)        // 66560 halfs
#define B_LDR 72                  // 64 + 8 pad halfs
#define SB_R (KCHUNK * B_LDR)     // 2304 halfs
#define SMEM_REC ((SA_R + 2 * SB_R) * 2)  // 142336 bytes

// proj smem: A,B double-buffered tiles (A 128x32, B 32x128)
#define A_LDP 40
#define B_LDP 136
#define SA_P (128 * A_LDP)        // 5120 halfs
#define SB_P (KCHUNK * B_LDP)     // 4352 halfs
#define SMEM_PROJ (2 * (SA_P + SB_P) * 2)  // 37888 bytes

// ---------------- device scratch (no cudaMalloc allowed) ----------------
// ONLY referenced in device code (host-arg binding of __device__ globals
// silently resolves to the host shadow on GB300 ATS — the R4/R5 bug).
__device__ __align__(1024) float g_Az[(size_t)Tdim * HB];   // 256 MiB
__device__ __align__(1024) float g_Ar[(size_t)Tdim * HB];   // 256 MiB
__device__ __align__(1024) __half g_xh[(size_t)Tdim * XT_STRIDE];  // 64 MiB
__device__ __align__(1024) __half g_Kh[Hdim * Hdim];
__device__ __align__(1024) __half g_Wh[Hdim * Hdim];
__device__ __align__(1024) __half g_Pzh[Hdim * INdim];
__device__ __align__(1024) __half g_Prh[Hdim * INdim];
__device__ __align__(1024) __half g_rh[HB];
__device__ __align__(1024) __half g_mh[HB];
__device__ __align__(1024) float g_G1p[KSPLIT * HB];
__device__ __align__(1024) float g_G2p[KSPLIT * HB];
__device__ unsigned long long g_barrier;  // monotonic, never reset

// ---------------- helpers ----------------
__device__ __forceinline__ float sigm(float x) {
    return 1.0f / (1.0f + __expf(-x));
}
__device__ __forceinline__ uint32_t s2u(const void* p) {
    return (uint32_t)__cvta_generic_to_shared(p);
}
__device__ __forceinline__ void cp_async16_ca(uint32_t saddr, const void* g) {
    asm volatile("cp.async.ca.shared.global [%0], [%1], 16;"
                 :: "r"(saddr), "l"(g));
}
__device__ __forceinline__ void cp_async16_cg(uint32_t saddr, const void* g) {
    asm volatile("cp.async.cg.shared.global [%0], [%1], 16;"
                 :: "r"(saddr), "l"(g));
}
__device__ __forceinline__ void cp_commit() {
    asm volatile("cp.async.commit_group;" ::: "memory");
}
template <int N>
__device__ __forceinline__ void cp_wait() {
    asm volatile("cp.async.wait_group %0;" :: "n"(N) : "memory");
}

// Grid barrier: monotonic counter; release-atomic arrive, acquire poll.
__device__ __forceinline__ void grid_sync() {
    __syncthreads();
    if (threadIdx.x == 0) {
        unsigned long long old;
        asm volatile("atom.release.gpu.global.add.u64 %0, [%1], 1;"
                     : "=l"(old) : "l"(&g_barrier) : "memory");
        const unsigned long long target = (old / NBLOCKS + 1) * NBLOCKS;
        unsigned long long cur;
        do {
            asm volatile("ld.acquire.gpu.global.u64 %0, [%1];"
                         : "=l"(cur) : "l"(&g_barrier) : "memory");
        } while (cur < target);
    }
    __syncthreads();
}

// ---------------- weight conversion: fp32 -> fp16 (one launch) -----------
__global__ __launch_bounds__(256) void conv_weights(
    const float* __restrict__ Km, const float* __restrict__ Wr,
    const float* __restrict__ Pz, const float* __restrict__ Pr)
{
    const size_t i = ((size_t)blockIdx.x * 256 + threadIdx.x) * 4;
    const float* src;
    __half* dst;
    size_t off;
    if (i < (size_t)Hdim * Hdim) { src = Km; dst = g_Kh; off = i; }
    else if (i < 2ull * Hdim * Hdim) {
        src = Wr; dst = g_Wh; off = i - (size_t)Hdim * Hdim;
    } else if (i < 2ull * Hdim * Hdim + (size_t)Hdim * INdim) {
        src = Pz; dst = g_Pzh; off = i - 2ull * Hdim * Hdim;
    } else {
        src = Pr; dst = g_Prh; off = i - 2ull * Hdim * Hdim - (size_t)Hdim * INdim;
    }
    float4 v = *(const float4*)&src[off];
    __half h[4] = { __float2half_rn(v.x), __float2half_rn(v.y),
                    __float2half_rn(v.z), __float2half_rn(v.w) };
    *(uint2*)&dst[off] = *(uint2*)h;
}

__global__ __launch_bounds__(256) void conv_x(const float* __restrict__ x) {
    const size_t i = ((size_t)blockIdx.x * 256 + threadIdx.x) * 4;
    float4 v = *(const float4*)&x[i];
    __half h[4] = { __float2half_rn(v.x), __float2half_rn(v.y),
                    __float2half_rn(v.z), __float2half_rn(v.w) };
    *(uint2*)&g_xh[i] = *(uint2*)h;
}

// ---------------- projection GEMM: Az/Ar[t] = P @ x_t --------------------
// Block tile 128x128, warp tile 32x64 (4x2 warps). grid (8, 2, 2*Tdim).
__global__ __launch_bounds__(256, 2) void proj_gemm() {
    extern __shared__ __half smh[];
    const int tid = threadIdx.x;
    const int warp = tid >> 5;
    const int wm = warp >> 1, wn = warp & 1;
    const int which = blockIdx.z & 1, q = blockIdx.z >> 1;
    const __half* A = which ? g_Prh : g_Pzh;
    const __half* B = g_xh + (size_t)q * XT_STRIDE;
    float* C = (which ? g_Ar : g_Az) + (size_t)q * HB;
    const int m0 = blockIdx.x * 128, n0 = blockIdx.y * 128;

    __half* const sA[2] = { smh, smh + SA_P };
    __half* const sB[2] = { smh + 2 * SA_P, smh + 2 * SA_P + SB_P };
    const uint32_t aB[2] = { s2u(sA[0]), s2u(sA[1]) };
    const uint32_t bB[2] = { s2u(sB[0]), s2u(sB[1]) };

    auto issue = [&](int c, int s) {
        const int kc = c * KCHUNK;
        // A tile: 128x32 halfs = 512 x 16B; 2/thread
#pragma unroll
        for (int i = 0; i < 2; ++i) {
            const int e = i * 256 + tid, r = e >> 2, f8 = e & 3;
            cp_async16_ca(aB[s] + (uint32_t)(r * A_LDP + f8 * 8) * 2,
                          A + (size_t)(m0 + r) * INdim + kc + f8 * 8);
        }
        // B tile: 32x128 halfs = 512 x 16B; 2/thread
#pragma unroll
        for (int i = 0; i < 2; ++i) {
            const int e = i * 256 + tid, r = e >> 4, f8 = e & 15;
            cp_async16_ca(bB[s] + (uint32_t)(r * B_LDP + f8 * 8) * 2,
                          B + (size_t)(kc + r) * Bdim + n0 + f8 * 8);
        }
        cp_commit();
    };

    wmma::fragment<wmma::accumulator, 16, 16, 16, float> acc[2][4];
#pragma unroll
    for (int i = 0; i < 2; ++i)
#pragma unroll
        for (int j = 0; j < 4; ++j) wmma::fill_fragment(acc[i][j], 0.0f);

    const int nChunks = INdim / KCHUNK;  // 16
    issue(0, 0);
    for (int c = 0; c < nChunks; ++c) {
        if (c + 1 < nChunks) { issue(c + 1, (c + 1) & 1); cp_wait<1>(); }
        else                 { cp_wait<0>(); }
        __syncthreads();
        const __half* cA = sA[c & 1];
        const __half* cB = sB[c & 1];
#pragma unroll
        for (int ks = 0; ks < 2; ++ks) {
            wmma::fragment<wmma::matrix_a, 16, 16, 16, __half,
                           wmma::row_major> af[2];
            wmma::fragment<wmma::matrix_b, 16, 16, 16, __half,
                           wmma::row_major> bf[4];
#pragma unroll
            for (int i = 0; i < 2; ++i)
                wmma::load_matrix_sync(af[i],
                    cA + (wm * 32 + i * 16) * A_LDP + ks * 16, A_LDP);
#pragma unroll
            for (int j = 0; j < 4; ++j)
                wmma::load_matrix_sync(bf[j],
                    cB + (ks * 16) * B_LDP + wn * 64 + j * 16, B_LDP);
#pragma unroll
            for (int i = 0; i < 2; ++i)
#pragma unroll
                for (int j = 0; j < 4; ++j)
                    wmma::mma_sync(acc[i][j], af[i], bf[j], acc[i][j]);
        }
        __syncthreads();
    }
    const int row = m0 + wm * 32, col = n0 + wn * 64;
#pragma unroll
    for (int i = 0; i < 2; ++i)
#pragma unroll
        for (int j = 0; j < 4; ++j)
            wmma::store_matrix_sync(
                C + (size_t)(row + i * 16) * Bdim + col + j * 16,
                acc[i][j], Bdim, wmma::mem_row_major);
}

// ---------------- persistent recurrence kernel ---------------------------
// 128 blocks x 256 threads, 1 block/SM (142KB smem). Each block's A-slice
// (128 rows x 512 K) lives in smem for ALL 256 steps; B double-buffered
// from L2 per step. State (v,X,U): 8 elements/thread in registers.
__global__ __launch_bounds__(256) void recurrence(
    const float* __restrict__ c_x, const float* __restrict__ c_u,
    const float* __restrict__ c_U, const float* __restrict__ gz,
    const float* __restrict__ br)
{
    extern __shared__ __half smh[];
    const int tid = threadIdx.x;
    const int bid = blockIdx.x;

    // ----- elem identity: 8 consecutive elements of [H][B] -----
    const int idx = (bid * 256 + tid) * 8;
    const int h = idx >> 8;
    const float zx = 0.001f + 0.099f * sigm(c_x[h]);
    const float zu = 0.001f + 0.099f * sigm(c_u[h]);
    const float Uc = 0.9f * sigm(c_U[h]);
    const float gzh = gz[h], brh = br[h];
    float v[8], X[8], U[8];
#pragma unroll
    for (int e = 0; e < 8; ++e) { v[e] = 0.f; X[e] = 1.f; U[e] = 0.9f; }

    // ----- gemm identity: 128 blocks = mb8 x nb4 x which2 x q2 -----
    const int which = bid & 1;
    const int q = (bid >> 1) & 1;
    const int nb = (bid >> 2) & 3;
    const int mb = bid >> 4;
    const int warp = tid >> 5;
    const int wm = warp >> 1, wn = warp & 1;
    const __half* Ag = which ? g_Wh : g_Kh;
    const __half* Bg = which ? g_mh : g_rh;
    float* Cg = (which ? g_G2p : g_G1p) + (size_t)q * HB;
    const int kStart = q * (Hdim / KSPLIT);   // 0 or 512
    const int m0 = mb * 128, n0 = nb * 64;

    __half* const sA = smh;                         // persistent 128 x A_LDR
    __half* const sB[2] = { smh + SA_R, smh + SA_R + SB_R };
    const uint32_t aBase = s2u(sA);
    const uint32_t bB[2] = { s2u(sB[0]), s2u(sB[1]) };

    // ----- one-time A-slice load: 128 rows x 512 halfs (64 x 16B/row) ----
    {
        const __half* Asrc = Ag + (size_t)m0 * Hdim + kStart;
#pragma unroll
        for (int i = 0; i < 32; ++i) {
            const int e = i * 256 + tid, r = e >> 6, g = e & 63;
            cp_async16_ca(aBase + (uint32_t)(r * A_LDR + g * 8) * 2,
                          Asrc + (size_t)r * Hdim + g * 8);
        }
        cp_commit();
        cp_wait<0>();
        __syncthreads();
    }

    auto issueB = [&](int c, int s) {
        const int kc = kStart + c * KCHUNK;
        const int r = tid >> 3, f8 = tid & 7;  // 32 rows x 8 granules
        cp_async16_cg(bB[s] + (uint32_t)(r * B_LDR + f8 * 8) * 2,
                      Bg + (size_t)(kc + r) * Bdim + n0 + f8 * 8);
        cp_commit();
    };

    for (int t = 0; t < Tdim; ++t) {
        // ===== elem phase =====
        if (t > 0) {
            const size_t off = (size_t)(t - 1) * HB + idx;
#pragma unroll
            for (int g = 0; g < 2; ++g) {
                const int i4 = idx + g * 4;
                float s1[4], s2[4], tmp[4], az[4], ar[4];
                *(float4*)s1 = __ldcg((const float4*)&g_G1p[i4]);
                *(float4*)s2 = __ldcg((const float4*)&g_G2p[i4]);
                *(float4*)tmp = __ldcg((const float4*)&g_G1p[HB + i4]);
#pragma unroll
                for (int e = 0; e < 4; ++e) s1[e] += tmp[e];
                *(float4*)tmp = __ldcg((const float4*)&g_G2p[HB + i4]);
#pragma unroll
                for (int e = 0; e < 4; ++e) s2[e] += tmp[e];
                *(float4*)az = *(const float4*)&g_Az[off + g * 4];
                *(float4*)ar = *(const float4*)&g_Ar[off + g * 4];
#pragma unroll
                for (int e = 0; e < 4; ++e) {
                    float zt = 0.1f * sigm(s1[e] + az[e] + gzh);
                    v[g * 4 + e] = (1.0f - zt) * v[g * 4 + e] +
                                   0.1f * (s2[e] + ar[e] + brh);
                }
                float vo[4] = { v[g * 4], v[g * 4 + 1], v[g * 4 + 2], v[g * 4 + 3] };
                *(float4*)&g_Az[off + g * 4] = *(float4*)vo;  // stage v
            }
        }
        {
            __half rr[8], mm[8];
#pragma unroll
            for (int e = 0; e < 8; ++e) {
                const float r = sigm(v[e]);
                float Xn = zx + (1.0f - zx) * X[e] - U[e] * X[e] * r;
                float Un = Uc * zu + (1.0f - zu) * U[e] + Uc * (1.0f - U[e]) * r;
                Un = fminf(fmaxf(Un, Uc), 1.0f);
                X[e] = Xn;
                U[e] = Un;
                rr[e] = __float2half_rn(r);
                mm[e] = __float2half_rn(Un * Xn * r);
            }
            *(uint4*)&g_rh[idx] = *(uint4*)rr;
            *(uint4*)&g_mh[idx] = *(uint4*)mm;
        }
        grid_sync();

        // ===== gemm phase: C_q = A_slice(smem) @ B[kStart:+512, n0:+64] =====
        {
            wmma::fragment<wmma::accumulator, 16, 16, 16, float> acc[2][2];
#pragma unroll
            for (int i = 0; i < 2; ++i)
#pragma unroll
                for (int j = 0; j < 2; ++j) wmma::fill_fragment(acc[i][j], 0.0f);

            const int nChunks = (Hdim / KSPLIT) / KCHUNK;  // 16
            issueB(0, 0);
            for (int c = 0; c < nChunks; ++c) {
                if (c + 1 < nChunks) { issueB(c + 1, (c + 1) & 1); cp_wait<1>(); }
                else                 { cp_wait<0>(); }
                __syncthreads();
                const __half* cB = sB[c & 1];
#pragma unroll
                for (int ks = 0; ks < 2; ++ks) {
                    wmma::fragment<wmma::matrix_a, 16, 16, 16, __half,
                                   wmma::row_major> af[2];
                    wmma::fragment<wmma::matrix_b, 16, 16, 16, __half,
                                   wmma::row_major> bf[2];
#pragma unroll
                    for (int i = 0; i < 2; ++i)
                        wmma::load_matrix_sync(af[i],
                            sA + (wm * 32 + i * 16) * A_LDR + c * 32 + ks * 16,
                            A_LDR);
#pragma unroll
                    for (int j = 0; j < 2; ++j)
                        wmma::load_matrix_sync(bf[j],
                            cB + (ks * 16) * B_LDR + wn * 32 + j * 16, B_LDR);
#pragma unroll
                    for (int i = 0; i < 2; ++i)
#pragma unroll
                        for (int j = 0; j < 2; ++j)
                            wmma::mma_sync(acc[i][j], af[i], bf[j], acc[i][j]);
                }
                __syncthreads();
            }
            const int row = m0 + wm * 32, col = n0 + wn * 32;
#pragma unroll
            for (int i = 0; i < 2; ++i)
#pragma unroll
                for (int j = 0; j < 2; ++j)
                    wmma::store_matrix_sync(
                        Cg + (size_t)(row + i * 16) * Bdim + col + j * 16,
                        acc[i][j], Bdim, wmma::mem_row_major);
        }
        grid_sync();
    }

    // ===== final epilogue: t = Tdim =====
    {
        const size_t off = (size_t)(Tdim - 1) * HB + idx;
#pragma unroll
        for (int g = 0; g < 2; ++g) {
            const int i4 = idx + g * 4;
            float s1[4], s2[4], tmp[4], az[4], ar[4];
            *(float4*)s1 = __ldcg((const float4*)&g_G1p[i4]);
            *(float4*)s2 = __ldcg((const float4*)&g_G2p[i4]);
            *(float4*)tmp = __ldcg((const float4*)&g_G1p[HB + i4]);
#pragma unroll
            for (int e = 0; e < 4; ++e) s1[e] += tmp[e];
            *(float4*)tmp = __ldcg((const float4*)&g_G2p[HB + i4]);
#pragma unroll
            for (int e = 0; e < 4; ++e) s2[e] += tmp[e];
            *(float4*)az = *(const float4*)&g_Az[off + g * 4];
            *(float4*)ar = *(const float4*)&g_Ar[off + g * 4];
#pragma unroll
            for (int e = 0; e < 4; ++e) {
                float zt = 0.1f * sigm(s1[e] + az[e] + gzh);
                v[g * 4 + e] = (1.0f - zt) * v[g * 4 + e] +
                               0.1f * (s2[e] + ar[e] + brh);
            }
            float vo[4] = { v[g * 4], v[g * 4 + 1], v[g * 4 + 2], v[g * 4 + 3] };
            *(float4*)&g_Az[off + g * 4] = *(float4*)vo;
        }
    }
}

// ---------------- final transpose: g_Az[t][h][b] -> out[t][b][h] ---------
__global__ __launch_bounds__(256) void transpose_out(float* __restrict__ out) {
    __shared__ float tile[32][33];
    const int t = blockIdx.z;
    const int h0 = blockIdx.y * 32;
    const int b0 = blockIdx.x * 32;
    const float* src = g_Az + (size_t)t * HB;
    float* dst = out + (size_t)t * HB;
    const int lx = threadIdx.x, ly = threadIdx.y;
#pragma unroll
    for (int i = 0; i < 32; i += 8)
        tile[ly + i][lx] = src[(size_t)(h0 + ly + i) * Bdim + b0 + lx];
    __syncthreads();
#pragma unroll
    for (int i = 0; i < 32; i += 8)
        dst[(size_t)(b0 + ly + i) * Hdim + h0 + lx] = tile[lx][ly + i];
}

// ---------------- launch ----------------
extern "C" void kernel_launch(void* const* d_in, const int* in_sizes, int n_in,
                              void* d_out, int out_size)
{
    const float* x   = (const float*)d_in[0];  // (T, IN, B)
    const float* c_x = (const float*)d_in[1];
    const float* c_u = (const float*)d_in[2];
    const float* c_U = (const float*)d_in[3];
    const float* w_r = (const float*)d_in[4];  // (H,H)
    const float* p_r = (const float*)d_in[5];  // (H,IN)
    const float* b_r = (const float*)d_in[6];
    const float* g_z = (const float*)d_in[7];
    const float* Km  = (const float*)d_in[8];  // (H,H)
    const float* p_z = (const float*)d_in[9];  // (H,IN)
    float* out = (float*)d_out;                // (T, B, H)

    cudaFuncSetAttribute(proj_gemm,
                         cudaFuncAttributeMaxDynamicSharedMemorySize, SMEM_PROJ);
    cudaFuncSetAttribute(recurrence,
                         cudaFuncAttributeMaxDynamicSharedMemorySize, SMEM_REC);

    conv_weights<<<(2 * Hdim * Hdim + 2 * Hdim * INdim) / 1024, 256>>>(
        Km, w_r, p_z, p_r);
    conv_x<<<(int)(((size_t)Tdim * XT_STRIDE) / 1024), 256>>>(x);
    proj_gemm<<<dim3(8, 2, 2 * Tdim), 256, SMEM_PROJ>>>();
    recurrence<<<NBLOCKS, 256, SMEM_REC>>>(c_x, c_u, c_U, g_z, b_r);
    transpose_out<<<dim3(Bdim / 32, Hdim / 32, Tdim), dim3(32, 8)>>>(out);
}

// round 11
// speedup vs baseline: 6.0960x; 1.1073x over previous
#include <cuda_runtime.h>
#include <cuda_fp16.h>
#include <mma.h>
#include <cstdint>
#include <math.h>

using namespace nvcuda;

#define Hdim 1024
#define INdim 512
#define Bdim 256
#define Tdim 256
#define HB (Hdim * Bdim)          // 262144 elements
#define KSPLIT 2
#define XT_STRIDE (INdim * Bdim)
#define NBLOCKS 128
#define KCHUNK 32

// recurrence smem: persistent A slice 128x512 + FULL B slice 512x64 halfs
#define A_LDR 520                 // 512 + 8 pad halfs
#define SA_R (128 * A_LDR)        // 66560 halfs = 133120 B
#define B_LDR 72                  // 64 + 8 pad halfs
#define SB_R (512 * B_LDR)        // 36864 halfs = 73728 B
#define SMEM_REC ((SA_R + SB_R) * 2)  // 206848 bytes

// proj smem: A,B double-buffered tiles (A 128x32, B 32x128)
#define A_LDP 40
#define B_LDP 136
#define SA_P (128 * A_LDP)
#define SB_P (KCHUNK * B_LDP)
#define SMEM_PROJ (2 * (SA_P + SB_P) * 2)  // 37888 bytes

// ---------------- device scratch (no cudaMalloc allowed) ----------------
// ONLY referenced in device code (host-arg binding of __device__ globals
// silently resolves to the host shadow on GB300 ATS — the R4/R5 bug).
__device__ __align__(1024) float g_Az[(size_t)Tdim * HB];   // 256 MiB
__device__ __align__(1024) float g_Ar[(size_t)Tdim * HB];   // 256 MiB
__device__ __align__(1024) __half g_xh[(size_t)Tdim * XT_STRIDE];  // 64 MiB
__device__ __align__(1024) __half g_Kh[Hdim * Hdim];
__device__ __align__(1024) __half g_Wh[Hdim * Hdim];
__device__ __align__(1024) __half g_Pzh[Hdim * INdim];
__device__ __align__(1024) __half g_Prh[Hdim * INdim];
__device__ __align__(1024) __half g_rh[HB];
__device__ __align__(1024) __half g_mh[HB];
__device__ __align__(1024) float g_G1p[KSPLIT * HB];
__device__ __align__(1024) float g_G2p[KSPLIT * HB];
__device__ unsigned long long g_barrier;  // monotonic, never reset

// ---------------- helpers ----------------
__device__ __forceinline__ float sigm(float x) {
    return 1.0f / (1.0f + __expf(-x));
}
__device__ __forceinline__ uint32_t s2u(const void* p) {
    return (uint32_t)__cvta_generic_to_shared(p);
}
__device__ __forceinline__ void cp_async16_ca(uint32_t saddr, const void* g) {
    asm volatile("cp.async.ca.shared.global [%0], [%1], 16;"
                 :: "r"(saddr), "l"(g));
}
__device__ __forceinline__ void cp_async16_cg(uint32_t saddr, const void* g) {
    asm volatile("cp.async.cg.shared.global [%0], [%1], 16;"
                 :: "r"(saddr), "l"(g));
}
__device__ __forceinline__ void cp_commit() {
    asm volatile("cp.async.commit_group;" ::: "memory");
}
template <int N>
__device__ __forceinline__ void cp_wait() {
    asm volatile("cp.async.wait_group %0;" :: "n"(N) : "memory");
}

// Grid barrier: monotonic counter; release-atomic arrive, acquire poll.
__device__ __forceinline__ void grid_sync() {
    __syncthreads();
    if (threadIdx.x == 0) {
        unsigned long long old;
        asm volatile("atom.release.gpu.global.add.u64 %0, [%1], 1;"
                     : "=l"(old) : "l"(&g_barrier) : "memory");
        const unsigned long long target = (old / NBLOCKS + 1) * NBLOCKS;
        unsigned long long cur;
        do {
            asm volatile("ld.acquire.gpu.global.u64 %0, [%1];"
                         : "=l"(cur) : "l"(&g_barrier) : "memory");
        } while (cur < target);
    }
    __syncthreads();
}

// ---------------- weight conversion: fp32 -> fp16 (one launch) -----------
__global__ __launch_bounds__(256) void conv_weights(
    const float* __restrict__ Km, const float* __restrict__ Wr,
    const float* __restrict__ Pz, const float* __restrict__ Pr)
{
    const size_t i = ((size_t)blockIdx.x * 256 + threadIdx.x) * 4;
    const float* src;
    __half* dst;
    size_t off;
    if (i < (size_t)Hdim * Hdim) { src = Km; dst = g_Kh; off = i; }
    else if (i < 2ull * Hdim * Hdim) {
        src = Wr; dst = g_Wh; off = i - (size_t)Hdim * Hdim;
    } else if (i < 2ull * Hdim * Hdim + (size_t)Hdim * INdim) {
        src = Pz; dst = g_Pzh; off = i - 2ull * Hdim * Hdim;
    } else {
        src = Pr; dst = g_Prh; off = i - 2ull * Hdim * Hdim - (size_t)Hdim * INdim;
    }
    float4 v = *(const float4*)&src[off];
    __half h[4] = { __float2half_rn(v.x), __float2half_rn(v.y),
                    __float2half_rn(v.z), __float2half_rn(v.w) };
    *(uint2*)&dst[off] = *(uint2*)h;
}

__global__ __launch_bounds__(256) void conv_x(const float* __restrict__ x) {
    const size_t i = ((size_t)blockIdx.x * 256 + threadIdx.x) * 4;
    float4 v = *(const float4*)&x[i];
    __half h[4] = { __float2half_rn(v.x), __float2half_rn(v.y),
                    __float2half_rn(v.z), __float2half_rn(v.w) };
    *(uint2*)&g_xh[i] = *(uint2*)h;
}

// ---------------- projection GEMM: Az/Ar[t] = P @ x_t --------------------
// Block tile 128x128, warp tile 32x64 (4x2 warps). grid (8, 2, 2*Tdim).
__global__ __launch_bounds__(256, 2) void proj_gemm() {
    extern __shared__ __half smh[];
    const int tid = threadIdx.x;
    const int warp = tid >> 5;
    const int wm = warp >> 1, wn = warp & 1;
    const int which = blockIdx.z & 1, q = blockIdx.z >> 1;
    const __half* A = which ? g_Prh : g_Pzh;
    const __half* B = g_xh + (size_t)q * XT_STRIDE;
    float* C = (which ? g_Ar : g_Az) + (size_t)q * HB;
    const int m0 = blockIdx.x * 128, n0 = blockIdx.y * 128;

    __half* const sA[2] = { smh, smh + SA_P };
    __half* const sB[2] = { smh + 2 * SA_P, smh + 2 * SA_P + SB_P };
    const uint32_t aB[2] = { s2u(sA[0]), s2u(sA[1]) };
    const uint32_t bB[2] = { s2u(sB[0]), s2u(sB[1]) };

    auto issue = [&](int c, int s) {
        const int kc = c * KCHUNK;
#pragma unroll
        for (int i = 0; i < 2; ++i) {
            const int e = i * 256 + tid, r = e >> 2, f8 = e & 3;
            cp_async16_ca(aB[s] + (uint32_t)(r * A_LDP + f8 * 8) * 2,
                          A + (size_t)(m0 + r) * INdim + kc + f8 * 8);
        }
#pragma unroll
        for (int i = 0; i < 2; ++i) {
            const int e = i * 256 + tid, r = e >> 4, f8 = e & 15;
            cp_async16_ca(bB[s] + (uint32_t)(r * B_LDP + f8 * 8) * 2,
                          B + (size_t)(kc + r) * Bdim + n0 + f8 * 8);
        }
        cp_commit();
    };

    wmma::fragment<wmma::accumulator, 16, 16, 16, float> acc[2][4];
#pragma unroll
    for (int i = 0; i < 2; ++i)
#pragma unroll
        for (int j = 0; j < 4; ++j) wmma::fill_fragment(acc[i][j], 0.0f);

    const int nChunks = INdim / KCHUNK;  // 16
    issue(0, 0);
    for (int c = 0; c < nChunks; ++c) {
        if (c + 1 < nChunks) { issue(c + 1, (c + 1) & 1); cp_wait<1>(); }
        else                 { cp_wait<0>(); }
        __syncthreads();
        const __half* cA = sA[c & 1];
        const __half* cB = sB[c & 1];
#pragma unroll
        for (int ks = 0; ks < 2; ++ks) {
            wmma::fragment<wmma::matrix_a, 16, 16, 16, __half,
                           wmma::row_major> af[2];
            wmma::fragment<wmma::matrix_b, 16, 16, 16, __half,
                           wmma::row_major> bf[4];
#pragma unroll
            for (int i = 0; i < 2; ++i)
                wmma::load_matrix_sync(af[i],
                    cA + (wm * 32 + i * 16) * A_LDP + ks * 16, A_LDP);
#pragma unroll
            for (int j = 0; j < 4; ++j)
                wmma::load_matrix_sync(bf[j],
                    cB + (ks * 16) * B_LDP + wn * 64 + j * 16, B_LDP);
#pragma unroll
            for (int i = 0; i < 2; ++i)
#pragma unroll
                for (int j = 0; j < 4; ++j)
                    wmma::mma_sync(acc[i][j], af[i], bf[j], acc[i][j]);
        }
        __syncthreads();
    }
    const int row = m0 + wm * 32, col = n0 + wn * 64;
#pragma unroll
    for (int i = 0; i < 2; ++i)
#pragma unroll
        for (int j = 0; j < 4; ++j)
            wmma::store_matrix_sync(
                C + (size_t)(row + i * 16) * Bdim + col + j * 16,
                acc[i][j], Bdim, wmma::mem_row_major);
}

// ---------------- persistent recurrence kernel ---------------------------
// 128 blocks x 256 threads, 1 block/SM (207KB smem). A-slice persistent in
// smem; FULL per-step B slice prefetched in 2 cp.async groups -> chunk loop
// has no internal syncs. Az/Ar prefetched into regs during gemm phase.
__global__ __launch_bounds__(256, 1) void recurrence(
    const float* __restrict__ c_x, const float* __restrict__ c_u,
    const float* __restrict__ c_U, const float* __restrict__ gz,
    const float* __restrict__ br)
{
    extern __shared__ __half smh[];
    const int tid = threadIdx.x;
    const int bid = blockIdx.x;

    // ----- elem identity: 8 consecutive elements of [H][B] -----
    const int idx = (bid * 256 + tid) * 8;
    const int h = idx >> 8;
    const float zx = 0.001f + 0.099f * sigm(c_x[h]);
    const float zu = 0.001f + 0.099f * sigm(c_u[h]);
    const float Uc = 0.9f * sigm(c_U[h]);
    const float gzh = gz[h], brh = br[h];
    float v[8], X[8], U[8];
#pragma unroll
    for (int e = 0; e < 8; ++e) { v[e] = 0.f; X[e] = 1.f; U[e] = 0.9f; }

    // ----- gemm identity: 128 blocks = mb8 x nb4 x which2 x q2 -----
    const int which = bid & 1;
    const int q = (bid >> 1) & 1;
    const int nb = (bid >> 2) & 3;
    const int mb = bid >> 4;
    const int warp = tid >> 5;
    const int wm = warp >> 1, wn = warp & 1;
    const __half* Ag = which ? g_Wh : g_Kh;
    const __half* Bg = which ? g_mh : g_rh;
    float* Cg = (which ? g_G2p : g_G1p) + (size_t)q * HB;
    const int kStart = q * (Hdim / KSPLIT);   // 0 or 512
    const int m0 = mb * 128, n0 = nb * 64;

    __half* const sA = smh;               // persistent 128 x A_LDR
    __half* const sB = smh + SA_R;        // full 512 x B_LDR
    const uint32_t aBase = s2u(sA);
    const uint32_t bBase = s2u(sB);

    // ----- one-time A-slice load -----
    {
        const __half* Asrc = Ag + (size_t)m0 * Hdim + kStart;
#pragma unroll
        for (int i = 0; i < 32; ++i) {
            const int e = i * 256 + tid, r = e >> 6, g = e & 63;
            cp_async16_ca(aBase + (uint32_t)(r * A_LDR + g * 8) * 2,
                          Asrc + (size_t)r * Hdim + g * 8);
        }
        cp_commit();
        cp_wait<0>();
        __syncthreads();
    }

    // per-chunk B load: 32 rows x 8 granules = 256 cp.async (1/thread)
    const int brow = tid >> 3, bg8 = tid & 7;
    auto issueB = [&](int c) {
        const int kc = kStart + c * KCHUNK;
        cp_async16_cg(
            bBase + (uint32_t)((c * KCHUNK + brow) * B_LDR + bg8 * 8) * 2,
            Bg + (size_t)(kc + brow) * Bdim + n0 + bg8 * 8);
    };

    // elem helper pieces inline in loop below.
    // ----- initial elem (t = 0): v=0 -> r, m -----
    {
        __half rr[8], mm[8];
#pragma unroll
        for (int e = 0; e < 8; ++e) {
            const float r = sigm(v[e]);
            float Xn = zx + (1.0f - zx) * X[e] - U[e] * X[e] * r;
            float Un = Uc * zu + (1.0f - zu) * U[e] + Uc * (1.0f - U[e]) * r;
            Un = fminf(fmaxf(Un, Uc), 1.0f);
            X[e] = Xn;
            U[e] = Un;
            rr[e] = __float2half_rn(r);
            mm[e] = __float2half_rn(Un * Xn * r);
        }
        *(uint4*)&g_rh[idx] = *(uint4*)rr;
        *(uint4*)&g_mh[idx] = *(uint4*)mm;
    }
    grid_sync();

    for (int t = 0; t < Tdim; ++t) {
        // ===== gemm phase: C_q = A_slice @ B[kStart:+512, n0:+64] =====
        float az[8], ar[8];
        {
            // prefetch FULL B: chunks 0-3 -> group 0, 4-15 -> group 1
#pragma unroll
            for (int c = 0; c < 4; ++c) issueB(c);
            cp_commit();
#pragma unroll
            for (int c = 4; c < 16; ++c) issueB(c);
            cp_commit();

            wmma::fragment<wmma::accumulator, 16, 16, 16, float> acc[2][2];
#pragma unroll
            for (int i = 0; i < 2; ++i)
#pragma unroll
                for (int j = 0; j < 2; ++j) wmma::fill_fragment(acc[i][j], 0.0f);

            cp_wait<1>();
            __syncthreads();
#pragma unroll 2
            for (int c = 0; c < 4; ++c) {
#pragma unroll
                for (int ks = 0; ks < 2; ++ks) {
                    wmma::fragment<wmma::matrix_a, 16, 16, 16, __half,
                                   wmma::row_major> af[2];
                    wmma::fragment<wmma::matrix_b, 16, 16, 16, __half,
                                   wmma::row_major> bf[2];
#pragma unroll
                    for (int i = 0; i < 2; ++i)
                        wmma::load_matrix_sync(af[i],
                            sA + (wm * 32 + i * 16) * A_LDR + c * 32 + ks * 16,
                            A_LDR);
#pragma unroll
                    for (int j = 0; j < 2; ++j)
                        wmma::load_matrix_sync(bf[j],
                            sB + (c * 32 + ks * 16) * B_LDR + wn * 32 + j * 16,
                            B_LDR);
#pragma unroll
                    for (int i = 0; i < 2; ++i)
#pragma unroll
                        for (int j = 0; j < 2; ++j)
                            wmma::mma_sync(acc[i][j], af[i], bf[j], acc[i][j]);
                }
            }
            cp_wait<0>();
            __syncthreads();
#pragma unroll 2
            for (int c = 4; c < 16; ++c) {
#pragma unroll
                for (int ks = 0; ks < 2; ++ks) {
                    wmma::fragment<wmma::matrix_a, 16, 16, 16, __half,
                                   wmma::row_major> af[2];
                    wmma::fragment<wmma::matrix_b, 16, 16, 16, __half,
                                   wmma::row_major> bf[2];
#pragma unroll
                    for (int i = 0; i < 2; ++i)
                        wmma::load_matrix_sync(af[i],
                            sA + (wm * 32 + i * 16) * A_LDR + c * 32 + ks * 16,
                            A_LDR);
#pragma unroll
                    for (int j = 0; j < 2; ++j)
                        wmma::load_matrix_sync(bf[j],
                            sB + (c * 32 + ks * 16) * B_LDR + wn * 32 + j * 16,
                            B_LDR);
#pragma unroll
                    for (int i = 0; i < 2; ++i)
#pragma unroll
                        for (int j = 0; j < 2; ++j)
                            wmma::mma_sync(acc[i][j], af[i], bf[j], acc[i][j]);
                }
            }
            const int row = m0 + wm * 32, col = n0 + wn * 32;
#pragma unroll
            for (int i = 0; i < 2; ++i)
#pragma unroll
                for (int j = 0; j < 2; ++j)
                    wmma::store_matrix_sync(
                        Cg + (size_t)(row + i * 16) * Bdim + col + j * 16,
                        acc[i][j], Bdim, wmma::mem_row_major);

            // prefetch next elem's Az/Ar (barrier-independent inputs)
            const size_t off = (size_t)t * HB + idx;
            *(float4*)&az[0] = *(const float4*)&g_Az[off];
            *(float4*)&az[4] = *(const float4*)&g_Az[off + 4];
            *(float4*)&ar[0] = *(const float4*)&g_Ar[off];
            *(float4*)&ar[4] = *(const float4*)&g_Ar[off + 4];
        }
        grid_sync();

        // ===== elem phase for step t+1 =====
        {
            const size_t off = (size_t)t * HB + idx;
            float s1[8], s2[8], tmp[4];
#pragma unroll
            for (int g = 0; g < 2; ++g) {
                *(float4*)&s1[g * 4] = __ldcg((const float4*)&g_G1p[idx + g * 4]);
                *(float4*)&s2[g * 4] = __ldcg((const float4*)&g_G2p[idx + g * 4]);
                *(float4*)tmp = __ldcg((const float4*)&g_G1p[HB + idx + g * 4]);
#pragma unroll
                for (int e = 0; e < 4; ++e) s1[g * 4 + e] += tmp[e];
                *(float4*)tmp = __ldcg((const float4*)&g_G2p[HB + idx + g * 4]);
#pragma unroll
                for (int e = 0; e < 4; ++e) s2[g * 4 + e] += tmp[e];
            }
#pragma unroll
            for (int e = 0; e < 8; ++e) {
                float zt = 0.1f * sigm(s1[e] + az[e] + gzh);
                v[e] = (1.0f - zt) * v[e] + 0.1f * (s2[e] + ar[e] + brh);
            }
            // stage v_t (streaming store, don't pollute L2)
            __stcs((float4*)&g_Az[off], *(float4*)&v[0]);
            __stcs((float4*)&g_Az[off + 4], *(float4*)&v[4]);

            if (t + 1 < Tdim) {
                __half rr[8], mm[8];
#pragma unroll
                for (int e = 0; e < 8; ++e) {
                    const float r = sigm(v[e]);
                    float Xn = zx + (1.0f - zx) * X[e] - U[e] * X[e] * r;
                    float Un = Uc * zu + (1.0f - zu) * U[e] +
                               Uc * (1.0f - U[e]) * r;
                    Un = fminf(fmaxf(Un, Uc), 1.0f);
                    X[e] = Xn;
                    U[e] = Un;
                    rr[e] = __float2half_rn(r);
                    mm[e] = __float2half_rn(Un * Xn * r);
                }
                *(uint4*)&g_rh[idx] = *(uint4*)rr;
                *(uint4*)&g_mh[idx] = *(uint4*)mm;
            }
        }
        if (t + 1 < Tdim) grid_sync();
    }
}

// ---------------- final transpose: g_Az[t][h][b] -> out[t][b][h] ---------
__global__ __launch_bounds__(256) void transpose_out(float* __restrict__ out) {
    __shared__ float tile[32][33];
    const int t = blockIdx.z;
    const int h0 = blockIdx.y * 32;
    const int b0 = blockIdx.x * 32;
    const float* src = g_Az + (size_t)t * HB;
    float* dst = out + (size_t)t * HB;
    const int lx = threadIdx.x, ly = threadIdx.y;
#pragma unroll
    for (int i = 0; i < 32; i += 8)
        tile[ly + i][lx] = src[(size_t)(h0 + ly + i) * Bdim + b0 + lx];
    __syncthreads();
#pragma unroll
    for (int i = 0; i < 32; i += 8)
        dst[(size_t)(b0 + ly + i) * Hdim + h0 + lx] = tile[lx][ly + i];
}

// ---------------- launch ----------------
extern "C" void kernel_launch(void* const* d_in, const int* in_sizes, int n_in,
                              void* d_out, int out_size)
{
    const float* x   = (const float*)d_in[0];  // (T, IN, B)
    const float* c_x = (const float*)d_in[1];
    const float* c_u = (const float*)d_in[2];
    const float* c_U = (const float*)d_in[3];
    const float* w_r = (const float*)d_in[4];  // (H,H)
    const float* p_r = (const float*)d_in[5];  // (H,IN)
    const float* b_r = (const float*)d_in[6];
    const float* g_z = (const float*)d_in[7];
    const float* Km  = (const float*)d_in[8];  // (H,H)
    const float* p_z = (const float*)d_in[9];  // (H,IN)
    float* out = (float*)d_out;                // (T, B, H)

    cudaFuncSetAttribute(proj_gemm,
                         cudaFuncAttributeMaxDynamicSharedMemorySize, SMEM_PROJ);
    cudaFuncSetAttribute(recurrence,
                         cudaFuncAttributeMaxDynamicSharedMemorySize, SMEM_REC);

    conv_weights<<<(2 * Hdim * Hdim + 2 * Hdim * INdim) / 1024, 256>>>(
        Km, w_r, p_z, p_r);
    conv_x<<<(int)(((size_t)Tdim * XT_STRIDE) / 1024), 256>>>(x);
    proj_gemm<<<dim3(8, 2, 2 * Tdim), 256, SMEM_PROJ>>>();
    recurrence<<<NBLOCKS, 256, SMEM_REC>>>(c_x, c_u, c_U, g_z, b_r);
    transpose_out<<<dim3(Bdim / 32, Hdim / 32, Tdim), dim3(32, 8)>>>(out);
}